// round 9
// baseline (speedup 1.0000x reference)
#include <cuda_runtime.h>
#include <cuda_bf16.h>
#include <stdint.h>

#define Bb 256
#define Tt 512
#define Ee 512
#define Hh 1024
#define G4 4096
#define Mm 1024
#define VOC 32001

#define GX 32              // n-tiles (32 h-cols -> N=128 with 4 gates)
#define GY 4               // batch groups (64 each -> M=64)
#define NT 16              // K-tiles of 64 over K=1024 (h only)
#define NRES 8             // resident W_hh K-tiles; 8..15 streamed
#define BTILE 16384        // 128 rows x 128B
#define ATILE 8192         // 64 rows x 128B
#define BSTR_OFF (NRES * BTILE)          // 131072
#define A_OFF    (BSTR_OFF + 3 * BTILE)  // 180224
#define SG_OFF   (A_OFF + 3 * ATILE)     // 204800
#define DYN_SMEM (SG_OFF + 16384)        // 221184
#define GT_DYN   98304                   // k_gtab: 3 stages x (16K A + 16K B)

// ---------------- static device scratch ----------------
__device__ __align__(16) __nv_bfloat16 g_emb16[(size_t)VOC * Ee];      // 32.8 MB
__device__ __align__(16) __nv_bfloat16 g_Wi[(size_t)G4 * Ee];          // 4.2 MB
__device__ __align__(16) __nv_bfloat16 g_Wh[(size_t)G4 * Hh];          // 8.4 MB
__device__ __align__(16) __nv_bfloat16 g_gtab[(size_t)VOC * G4];       // 262 MB: Gtab[v] = W_ih @ emb[v]
__device__ float         g_bias[G4];
__device__ __align__(16) __nv_bfloat16 g_h[3][Bb * Hh];                // TRIPLE buffered (skew<=1 tolerant)
__device__ float         g_hn[Bb * Hh];
__device__ float         g_z[Bb * Mm];
__device__ int           g_flag[4][32][32];                            // [gy][producer bx][pad]

// ---------------- setup kernels ----------------
__global__ void k_setup_emb(const float* __restrict__ emb) {
    int i4 = blockIdx.x * blockDim.x + threadIdx.x;
    const int n4 = (VOC * Ee) / 4;
    if (i4 >= n4) return;
    float4 v = reinterpret_cast<const float4*>(emb)[i4];
    reinterpret_cast<__nv_bfloat162*>(g_emb16)[i4 * 2 + 0] = __floats2bfloat162_rn(v.x, v.y);
    reinterpret_cast<__nv_bfloat162*>(g_emb16)[i4 * 2 + 1] = __floats2bfloat162_rn(v.z, v.w);
}

__global__ void k_setup_w(const float* __restrict__ Wih, const float* __restrict__ Whh) {
    int i4 = blockIdx.x * blockDim.x + threadIdx.x;
    const int nW = (G4 * Hh) / 4;
    if (i4 < nW) {
        float4 v = *reinterpret_cast<const float4*>(&Whh[(size_t)i4 * 4]);
        reinterpret_cast<__nv_bfloat162*>(g_Wh)[i4 * 2 + 0] = __floats2bfloat162_rn(v.x, v.y);
        reinterpret_cast<__nv_bfloat162*>(g_Wh)[i4 * 2 + 1] = __floats2bfloat162_rn(v.z, v.w);
    }
    const int nI = (G4 * Ee) / 4;
    if (i4 < nI) {
        float4 v = *reinterpret_cast<const float4*>(&Wih[(size_t)i4 * 4]);
        reinterpret_cast<__nv_bfloat162*>(g_Wi)[i4 * 2 + 0] = __floats2bfloat162_rn(v.x, v.y);
        reinterpret_cast<__nv_bfloat162*>(g_Wi)[i4 * 2 + 1] = __floats2bfloat162_rn(v.z, v.w);
    }
}

__global__ void k_setup_state(const float* __restrict__ h0,
                              const float* __restrict__ b_ih, const float* __restrict__ b_hh) {
    int i = blockIdx.x * blockDim.x + threadIdx.x;
    if (i < Bb * Hh) g_h[0][i] = __float2bfloat16(h0[i]);
    if (i < G4)      g_bias[i] = b_ih[i] + b_hh[i];
    if (i < 4 * 32 * 32) reinterpret_cast<int*>(g_flag)[i] = 0;
}

// ---------------- helpers ----------------
__device__ __forceinline__ void mma16816(float* d, const uint32_t* a, const uint32_t* b) {
    asm volatile(
        "mma.sync.aligned.m16n8k16.row.col.f32.bf16.bf16.f32 "
        "{%0,%1,%2,%3}, {%4,%5,%6,%7}, {%8,%9}, {%0,%1,%2,%3};\n"
        : "+f"(d[0]), "+f"(d[1]), "+f"(d[2]), "+f"(d[3])
        : "r"(a[0]), "r"(a[1]), "r"(a[2]), "r"(a[3]), "r"(b[0]), "r"(b[1]));
}

#define CP16(dst, src) \
    asm volatile("cp.async.cg.shared.global [%0], [%1], 16;\n" :: "r"(dst), "l"(src))
#define CP_COMMIT() asm volatile("cp.async.commit_group;\n")
#define LDM_X4(r0, r1, r2, r3, addr) \
    asm volatile("ldmatrix.sync.aligned.m8n8.x4.shared.b16 {%0,%1,%2,%3}, [%4];\n" \
                 : "=r"(r0), "=r"(r1), "=r"(r2), "=r"(r3) : "r"(addr))

__device__ __forceinline__ float sigf(float x) {
    return __fdividef(1.0f, 1.0f + __expf(-x));
}
__device__ __forceinline__ float tanhfast(float x) {
    return __fdividef(2.0f, 1.0f + __expf(-2.0f * x)) - 1.0f;
}

// ---------------- Gtab GEMM: Gtab[v][n] = sum_k emb16[v][k] * W_ih[n][k] ----------------
__global__ __launch_bounds__(256) void k_gtab() {
    extern __shared__ __align__(16) char gsm[];
    const uint32_t smb = (uint32_t)__cvta_generic_to_shared(gsm);
    const int tid = threadIdx.x;
    const int lane = tid & 31;
    const int wid = tid >> 5;
    const int n0 = blockIdx.x * 128;
    const int vb = blockIdx.y * 128;

    auto load = [&](int kt) {
#pragma unroll
        for (int i = 0; i < 4; ++i) {
            int id = tid + i * 256;
            int r = id >> 3, c = id & 7;
            int v = vb + r; if (v > VOC - 1) v = VOC - 1;
            uint32_t sw = (uint32_t)(r * 128 + ((c ^ (r & 7)) << 4));
            CP16(smb + (kt % 3) * 16384u + sw, g_emb16 + (size_t)v * Ee + kt * 64 + c * 8);
            CP16(smb + 49152u + (kt % 3) * 16384u + sw, g_Wi + (size_t)(n0 + r) * Ee + kt * 64 + c * 8);
        }
        CP_COMMIT();
    };

    const int mbase = (wid >> 2) * 64;
    const int nbase = (wid & 3) * 32;
    float acc[4][4][4];
#pragma unroll
    for (int mt = 0; mt < 4; ++mt)
#pragma unroll
        for (int nt = 0; nt < 4; ++nt)
#pragma unroll
            for (int e = 0; e < 4; ++e) acc[mt][nt][e] = 0.0f;

    load(0);
    load(1);
    for (int kt = 0; kt < 8; ++kt) {
        if (kt < 7) asm volatile("cp.async.wait_group 1;\n");
        else        asm volatile("cp.async.wait_group 0;\n");
        __syncthreads();
        if (kt + 2 < 8) load(kt + 2);
        const uint32_t ab = smb + (kt % 3) * 16384u;
        const uint32_t bbs = smb + 49152u + (kt % 3) * 16384u;
#pragma unroll
        for (int ks = 0; ks < 64; ks += 16) {
            uint32_t a[4][4];
#pragma unroll
            for (int mt = 0; mt < 4; ++mt) {
                int r = mbase + mt * 16 + (lane & 15);
                int ch = (ks >> 3) + (lane >> 4);
                LDM_X4(a[mt][0], a[mt][1], a[mt][2], a[mt][3],
                       ab + (uint32_t)(r * 128 + ((ch ^ (r & 7)) << 4)));
            }
            uint32_t b[2][4];
#pragma unroll
            for (int bt = 0; bt < 2; ++bt) {
                int gq = lane >> 3;
                int rn = nbase + bt * 16 + ((gq >> 1) << 3) + (lane & 7);
                int ch = (ks >> 3) + (gq & 1);
                LDM_X4(b[bt][0], b[bt][1], b[bt][2], b[bt][3],
                       bbs + (uint32_t)(rn * 128 + ((ch ^ (rn & 7)) << 4)));
            }
#pragma unroll
            for (int mt = 0; mt < 4; ++mt)
#pragma unroll
                for (int nt = 0; nt < 4; ++nt) {
                    uint32_t bf[2] = { b[nt >> 1][(nt & 1) * 2], b[nt >> 1][(nt & 1) * 2 + 1] };
                    mma16816(acc[mt][nt], a[mt], bf);
                }
        }
        __syncthreads();
    }

    const int fr = lane >> 2, fc = (lane & 3) * 2;
#pragma unroll
    for (int mt = 0; mt < 4; ++mt)
#pragma unroll
        for (int nt = 0; nt < 4; ++nt) {
            int c = n0 + nbase + nt * 8 + fc;
            int v0 = vb + mbase + mt * 16 + fr;
            int v1 = v0 + 8;
            if (v0 < VOC)
                *reinterpret_cast<__nv_bfloat162*>(g_gtab + (size_t)v0 * G4 + c) =
                    __floats2bfloat162_rn(acc[mt][nt][0], acc[mt][nt][1]);
            if (v1 < VOC)
                *reinterpret_cast<__nv_bfloat162*>(g_gtab + (size_t)v1 * G4 + c) =
                    __floats2bfloat162_rn(acc[mt][nt][2], acc[mt][nt][3]);
        }
}

// ---------------- persistent fused LSTM (flag-pipelined, no global barrier) ----------------
// grid (32, 4). Block tile: gates[64, 128] = h @ Wh_slice^T + Gtab + bias.
// Warps 0-3: mma m32n64 (2x2) + epilogue. Warps 4-7: cp.async loaders.
// h triple-buffered; per-producer flags gate each A tile (skew <= 1 provable).
__global__ void __launch_bounds__(256, 1)
k_lstm_main(const int* __restrict__ x, const int* __restrict__ x_index,
            const float* __restrict__ c0) {
    extern __shared__ __align__(16) char dynsm[];
    __shared__ float s_bias[128];

    const int tid = threadIdx.x;
    const int lane = tid & 31;
    const int wid = tid >> 5;
    const int gy = blockIdx.y;
    const int bx = blockIdx.x;
    const int b0 = gy * 64;
    const int hc0 = bx * 32;

    const uint32_t smb = (uint32_t)__cvta_generic_to_shared(dynsm);
    const uint32_t Bres = smb;
    const uint32_t Bstr = smb + BSTR_OFF;
    const uint32_t Ab   = smb + A_OFF;
    const uint32_t sGb  = smb + SG_OFF;
    float* sD = reinterpret_cast<float*>(dynsm + BSTR_OFF);   // overlays Bstr (33792B <= 49152B)
    const __nv_bfloat16* sG = reinterpret_cast<const __nv_bfloat16*>(dynsm + SG_OFF);

    if (tid < 128) s_bias[tid] = g_bias[(tid >> 5) * Hh + hc0 + (tid & 31)];

    // ---- resident Wh tiles 0..7 ----
    for (int i = tid; i < NRES * 1024; i += 256) {
        int kt = i >> 10, rem = i & 1023, n = rem >> 3, c = rem & 7;
        const __nv_bfloat16* src =
            g_Wh + (size_t)((n >> 5) * Hh + hc0 + (n & 31)) * Hh + kt * 64 + c * 8;
        CP16(Bres + (uint32_t)(kt * BTILE + n * 128 + ((c ^ (n & 7)) << 4)), src);
    }
    CP_COMMIT();
    asm volatile("cp.async.wait_group 0;\n");
    __syncthreads();

    // ---- loader assignments (warps 4-7) ----
    const bool loader = (wid >= 4);
    const int l7 = tid & 127;
    const int rb = l7 >> 3;   // 0..15
    const int cc = l7 & 7;
    uint32_t adst[4];
#pragma unroll
    for (int i = 0; i < 4; ++i) {
        int r = rb + 16 * i;
        adst[i] = (uint32_t)(r * 128 + ((cc ^ (r & 7)) << 4));
    }
    uint32_t bdst[8];
#pragma unroll
    for (int i = 0; i < 8; ++i) {
        int r = rb + 16 * i;
        bdst[i] = (uint32_t)(r * 128 + ((cc ^ (r & 7)) << 4));
    }
    const int sg_r = l7 >> 1;
    const int sg_cb = (l7 & 1) * 8;

    // ---- mma warp config: 2(m) x 2(n), warp tile m32 x n64 ----
    const int mbase = ((wid >> 1) & 1) * 32;
    const int nbase = (wid & 1) * 64;

    // ---- epilogue state (mma warps): 16 (bb, jj) items per thread ----
    float creg[16];
    int xib[16];
    if (wid < 4) {
        const int jj = lane;
#pragma unroll
        for (int w = 0; w < 16; ++w) {
            int bb = w * 4 + wid;
            int b = b0 + bb;
            xib[w] = x_index[b];
            creg[w] = c0[(size_t)b * Hh + hc0 + jj];
        }
    }

    // tile kt of step s reads g_h[s%3] cols kt*64.., produced by blocks 2kt, 2kt+1
    auto load_tile = [&](int kt, int s) {
        if (loader) {
            if ((tid & 31) == 0) {
                int v;
                const int* f0 = &g_flag[gy][2 * kt][0];
                const int* f1 = &g_flag[gy][2 * kt + 1][0];
                do { asm volatile("ld.acquire.gpu.u32 %0, [%1];" : "=r"(v) : "l"(f0)); } while (v < s);
                do { asm volatile("ld.acquire.gpu.u32 %0, [%1];" : "=r"(v) : "l"(f1)); } while (v < s);
            }
            __syncwarp();
            const uint32_t st = Ab + (uint32_t)(kt % 3) * ATILE;
            const __nv_bfloat16* hrd = g_h[s % 3];
#pragma unroll
            for (int i = 0; i < 4; ++i)
                CP16(st + adst[i], hrd + (size_t)(b0 + rb + 16 * i) * Hh + kt * 64 + cc * 8);
            if (kt >= NRES) {
                const uint32_t bs = Bstr + (uint32_t)(kt % 3) * BTILE;
#pragma unroll
                for (int i = 0; i < 8; ++i) {
                    int n = rb + 16 * i;
                    const __nv_bfloat16* src =
                        g_Wh + (size_t)((n >> 5) * Hh + hc0 + (n & 31)) * Hh + kt * 64 + cc * 8;
                    CP16(bs + bdst[i], src);
                }
            }
        }
        CP_COMMIT();
    };

    auto sG_load = [&](int s) {
        if (loader) {
            int tok = x[(size_t)(b0 + sg_r) * Tt + s];
            const __nv_bfloat16* gr = g_gtab + (size_t)tok * G4;
#pragma unroll
            for (int q = 0; q < 8; ++q) {
                int c = sg_cb + q;
                CP16(sGb + (uint32_t)(sg_r * 256 + c * 16), gr + (c >> 2) * Hh + hc0 + (c & 3) * 8);
            }
        }
        CP_COMMIT();
    };

    // prologue for step 0: order must match steady state [tile0, tile1, sG]
    load_tile(0, 0);
    load_tile(1, 0);
    sG_load(0);

    for (int t = 0; t < Tt; ++t) {
        float acc[2][8][4];
#pragma unroll
        for (int mt = 0; mt < 2; ++mt)
#pragma unroll
            for (int nt = 0; nt < 8; ++nt)
#pragma unroll
                for (int e = 0; e < 4; ++e) acc[mt][nt][e] = 0.0f;

        for (int it = 0; it < NT; ++it) {
            // loader ledger at wait: it=0:{t0,t1,sG} it=1:{t1,sG,t2} it>=2:{sG?,t_it,t_it+1}
            if (it <= 1)           asm volatile("cp.async.wait_group 2;\n");
            else if (it < NT - 1)  asm volatile("cp.async.wait_group 1;\n");
            else                   asm volatile("cp.async.wait_group 0;\n");
            __syncthreads();
            if (it + 2 < NT) load_tile(it + 2, t);

            if (wid < 4) {
                const uint32_t ab = Ab + (uint32_t)(it % 3) * ATILE;
                const uint32_t bb = (it < NRES) ? (Bres + (uint32_t)it * BTILE)
                                                : (Bstr + (uint32_t)(it % 3) * BTILE);
#pragma unroll
                for (int ks = 0; ks < 64; ks += 16) {
                    uint32_t a[2][4];
#pragma unroll
                    for (int mt = 0; mt < 2; ++mt) {
                        int r = mbase + mt * 16 + (lane & 15);
                        int ch = (ks >> 3) + (lane >> 4);
                        LDM_X4(a[mt][0], a[mt][1], a[mt][2], a[mt][3],
                               ab + (uint32_t)(r * 128 + ((ch ^ (r & 7)) << 4)));
                    }
                    uint32_t b[4][4];
#pragma unroll
                    for (int bt = 0; bt < 4; ++bt) {
                        int gq = lane >> 3;
                        int rn = nbase + bt * 16 + ((gq >> 1) << 3) + (lane & 7);
                        int ch = (ks >> 3) + (gq & 1);
                        LDM_X4(b[bt][0], b[bt][1], b[bt][2], b[bt][3],
                               bb + (uint32_t)(rn * 128 + ((ch ^ (rn & 7)) << 4)));
                    }
#pragma unroll
                    for (int mt = 0; mt < 2; ++mt)
#pragma unroll
                        for (int nt = 0; nt < 8; ++nt) {
                            uint32_t bf[2] = { b[nt >> 1][(nt & 1) * 2], b[nt >> 1][(nt & 1) * 2 + 1] };
                            mma16816(acc[mt][nt], a[mt], bf);
                        }
                }
            }
        }
        __syncthreads();   // all tiles consumed; A stages 0/1 and Bstr (sD) reusable

        if (wid < 4) {
            // ---- stage D: sD[m][n], rows padded to 132 floats (overlays Bstr) ----
            const int fr = lane >> 2, fc2 = (lane & 3) * 2;
#pragma unroll
            for (int mt = 0; mt < 2; ++mt)
#pragma unroll
                for (int nt = 0; nt < 8; ++nt) {
                    int m = mbase + mt * 16 + fr;
                    int n = nbase + nt * 8 + fc2;
                    sD[m * 132 + n]           = acc[mt][nt][0];
                    sD[m * 132 + n + 1]       = acc[mt][nt][1];
                    sD[(m + 8) * 132 + n]     = acc[mt][nt][2];
                    sD[(m + 8) * 132 + n + 1] = acc[mt][nt][3];
                }
            asm volatile("bar.sync 1, 128;" ::: "memory");

            // ---- pointwise LSTM update: 4 warps, 16 items/thread ----
            const int jj = lane;
            __nv_bfloat16* hwr = g_h[(t + 1) % 3];
#pragma unroll
            for (int w = 0; w < 16; ++w) {
                int bb = w * 4 + wid;
                int b = b0 + bb;
                const float* row = sD + bb * 132;
                const __nv_bfloat16* grow = sG + bb * 128;
                float ig = row[jj]      + __bfloat162float(grow[jj])      + s_bias[jj];
                float fg = row[32 + jj] + __bfloat162float(grow[32 + jj]) + s_bias[32 + jj];
                float gg = row[64 + jj] + __bfloat162float(grow[64 + jj]) + s_bias[64 + jj];
                float og = row[96 + jj] + __bfloat162float(grow[96 + jj]) + s_bias[96 + jj];
                float cv = sigf(fg) * creg[w] + sigf(ig) * tanhfast(gg);
                creg[w] = cv;
                float hv = sigf(og) * tanhfast(cv);
                hwr[(size_t)b * Hh + hc0 + jj] = __float2bfloat16(hv);
                if (xib[w] == t) g_hn[(size_t)b * Hh + hc0 + jj] = hv;
            }
            asm volatile("bar.sync 1, 128;" ::: "memory");
            if (tid == 0) {
                asm volatile("membar.gl;" ::: "memory");
                asm volatile("st.relaxed.gpu.global.u32 [%0], %1;"
                             :: "l"(&g_flag[gy][bx][0]), "r"(t + 1) : "memory");
            }
        } else {
            // ---- loaders: prefetch next step's first A tiles DURING epilogue ----
            if (t + 1 < Tt) {
                load_tile(0, t + 1);
                load_tile(1, t + 1);
            }
        }
        __syncthreads();   // loaders see pointwise done (sG free); mma see loads issued
        if (t + 1 < Tt) sG_load(t + 1);
    }
}

// ---------------- fc1: z = tanh(hn @ fc1_w^T + fc1_b), fp32 ----------------
__global__ __launch_bounds__(256) void k_fc1(const float* __restrict__ fc1_w,
                                             const float* __restrict__ fc1_b) {
    __shared__ float sA[16][68];
    __shared__ float sB[16][68];
    const int tid = threadIdx.x;
    const int b0 = blockIdx.y * 64;
    const int n0 = blockIdx.x * 64;
    const int tx = tid & 15, ty = tid >> 4;
    const int lr = tid & 63;
    const int lc4 = (tid >> 6) * 4;

    float acc[4][4];
#pragma unroll
    for (int i = 0; i < 4; ++i)
#pragma unroll
        for (int jn = 0; jn < 4; ++jn) acc[i][jn] = 0.0f;

    for (int k0 = 0; k0 < Hh; k0 += 16) {
        float4 va = *reinterpret_cast<const float4*>(&g_hn[(size_t)(b0 + lr) * Hh + k0 + lc4]);
        float4 vb = *reinterpret_cast<const float4*>(&fc1_w[(size_t)(n0 + lr) * Hh + k0 + lc4]);
        __syncthreads();
        sA[lc4 + 0][lr] = va.x; sA[lc4 + 1][lr] = va.y; sA[lc4 + 2][lr] = va.z; sA[lc4 + 3][lr] = va.w;
        sB[lc4 + 0][lr] = vb.x; sB[lc4 + 1][lr] = vb.y; sB[lc4 + 2][lr] = vb.z; sB[lc4 + 3][lr] = vb.w;
        __syncthreads();
#pragma unroll
        for (int k = 0; k < 16; ++k) {
            float4 ra4 = *reinterpret_cast<const float4*>(&sA[k][ty * 4]);
            float4 rb4 = *reinterpret_cast<const float4*>(&sB[k][tx * 4]);
            float ra[4] = {ra4.x, ra4.y, ra4.z, ra4.w};
            float rb[4] = {rb4.x, rb4.y, rb4.z, rb4.w};
#pragma unroll
            for (int i = 0; i < 4; ++i)
#pragma unroll
                for (int jn = 0; jn < 4; ++jn) acc[i][jn] += ra[i] * rb[jn];
        }
    }
#pragma unroll
    for (int i = 0; i < 4; ++i)
#pragma unroll
        for (int jn = 0; jn < 4; ++jn) {
            int bb = b0 + ty * 4 + i;
            int nn = n0 + tx * 4 + jn;
            g_z[(size_t)bb * Mm + nn] = tanhf(acc[i][jn] + fc1_b[nn]);
        }
}

// ---------------- fc2 + log_softmax (O=2) ----------------
__global__ __launch_bounds__(128) void k_fc2(const float* __restrict__ fc2_w,
                                             const float* __restrict__ fc2_b,
                                             float* __restrict__ out) {
    const int b = blockIdx.x;
    const int tid = threadIdx.x;
    float p0 = 0.f, p1 = 0.f;
    for (int k = tid; k < Mm; k += 128) {
        float zv = g_z[(size_t)b * Mm + k];
        p0 += zv * fc2_w[k];
        p1 += zv * fc2_w[Mm + k];
    }
#pragma unroll
    for (int off = 16; off; off >>= 1) {
        p0 += __shfl_down_sync(0xffffffffu, p0, off);
        p1 += __shfl_down_sync(0xffffffffu, p1, off);
    }
    __shared__ float s0[4], s1[4];
    if ((tid & 31) == 0) { s0[tid >> 5] = p0; s1[tid >> 5] = p1; }
    __syncthreads();
    if (tid == 0) {
        float l0 = s0[0] + s0[1] + s0[2] + s0[3] + fc2_b[0];
        float l1 = s1[0] + s1[1] + s1[2] + s1[3] + fc2_b[1];
        float mx = fmaxf(l0, l1);
        float lse = mx + logf(expf(l0 - mx) + expf(l1 - mx));
        out[b * 2 + 0] = l0 - lse;
        out[b * 2 + 1] = l1 - lse;
    }
}

// ---------------- launch ----------------
extern "C" void kernel_launch(void* const* d_in, const int* in_sizes, int n_in,
                              void* d_out, int out_size) {
    const int*   x       = (const int*)d_in[0];
    const int*   x_index = (const int*)d_in[1];
    const float* emb     = (const float*)d_in[2];
    const float* W_ih    = (const float*)d_in[3];
    const float* W_hh    = (const float*)d_in[4];
    const float* b_ih    = (const float*)d_in[5];
    const float* b_hh    = (const float*)d_in[6];
    const float* fc1_w   = (const float*)d_in[7];
    const float* fc1_b   = (const float*)d_in[8];
    const float* fc2_w   = (const float*)d_in[9];
    const float* fc2_b   = (const float*)d_in[10];
    const float* h0      = (const float*)d_in[11];
    const float* c0      = (const float*)d_in[12];
    float* out = (float*)d_out;

    (void)in_sizes; (void)n_in; (void)out_size;

    cudaFuncSetAttribute(k_lstm_main, cudaFuncAttributeMaxDynamicSharedMemorySize, DYN_SMEM);
    cudaFuncSetAttribute(k_gtab, cudaFuncAttributeMaxDynamicSharedMemorySize, GT_DYN);

    k_setup_emb<<<(VOC * Ee / 4 + 255) / 256, 256>>>(emb);
    k_setup_w<<<(G4 * Hh / 4 + 255) / 256, 256>>>(W_ih, W_hh);
    k_setup_state<<<(Bb * Hh + 255) / 256, 256>>>(h0, b_ih, b_hh);

    k_gtab<<<dim3(G4 / 128, (VOC + 127) / 128), 256, GT_DYN>>>();

    k_lstm_main<<<dim3(GX, GY), 256, DYN_SMEM>>>(x, x_index, c0);

    k_fc1<<<dim3(Mm / 64, Bb / 64), 256>>>(fc1_w, fc1_b);
    k_fc2<<<Bb, 128>>>(fc2_w, fc2_b, out);
}

// round 10
// speedup vs baseline: 1.4781x; 1.4781x over previous
#include <cuda_runtime.h>
#include <cuda_bf16.h>
#include <stdint.h>

#define Bb 256
#define Tt 512
#define Ee 512
#define Hh 1024
#define G4 4096
#define Mm 1024
#define VOC 32001

#define GX 32              // n-tiles (32 h-cols -> N=128 with 4 gates)
#define GY 4               // batch groups (64 each -> M=64)
#define NT 16              // K-tiles of 64 over K=1024 (h only)
#define NRES 8             // resident W_hh K-tiles; 8..15 streamed
#define BTILE 16384        // 128 rows x 128B
#define ATILE 8192         // 64 rows x 128B
#define BSTR_OFF (NRES * BTILE)          // 131072
#define A_OFF    (BSTR_OFF + 3 * BTILE)  // 180224
#define SG_OFF   (A_OFF + 3 * ATILE)     // 204800
#define DYN_SMEM (SG_OFF + 16384)        // 221184
#define GT_DYN   98304                   // k_gtab: 3 stages x (16K A + 16K B)

// ---------------- static device scratch ----------------
__device__ __align__(16) __nv_bfloat16 g_emb16[(size_t)VOC * Ee];      // 32.8 MB
__device__ __align__(16) __nv_bfloat16 g_Wi[(size_t)G4 * Ee];          // 4.2 MB
__device__ __align__(16) __nv_bfloat16 g_Wh[(size_t)G4 * Hh];          // 8.4 MB
__device__ __align__(16) __nv_bfloat16 g_gtab[(size_t)VOC * G4];       // 262 MB: Gtab[v] = W_ih @ emb[v]
__device__ float         g_bias[G4];
__device__ __align__(16) __nv_bfloat16 g_h[2][Bb * Hh];                // double buffered (full barrier/step)
__device__ float         g_hn[Bb * Hh];
__device__ float         g_z[Bb * Mm];
__device__ __align__(128) int g_flag[4][32];                           // [gy][bx] step-completion flags

// ---------------- setup kernels ----------------
__global__ void k_setup_emb(const float* __restrict__ emb) {
    int i4 = blockIdx.x * blockDim.x + threadIdx.x;
    const int n4 = (VOC * Ee) / 4;
    if (i4 >= n4) return;
    float4 v = reinterpret_cast<const float4*>(emb)[i4];
    reinterpret_cast<__nv_bfloat162*>(g_emb16)[i4 * 2 + 0] = __floats2bfloat162_rn(v.x, v.y);
    reinterpret_cast<__nv_bfloat162*>(g_emb16)[i4 * 2 + 1] = __floats2bfloat162_rn(v.z, v.w);
}

__global__ void k_setup_w(const float* __restrict__ Wih, const float* __restrict__ Whh) {
    int i4 = blockIdx.x * blockDim.x + threadIdx.x;
    const int nW = (G4 * Hh) / 4;
    if (i4 < nW) {
        float4 v = *reinterpret_cast<const float4*>(&Whh[(size_t)i4 * 4]);
        reinterpret_cast<__nv_bfloat162*>(g_Wh)[i4 * 2 + 0] = __floats2bfloat162_rn(v.x, v.y);
        reinterpret_cast<__nv_bfloat162*>(g_Wh)[i4 * 2 + 1] = __floats2bfloat162_rn(v.z, v.w);
    }
    const int nI = (G4 * Ee) / 4;
    if (i4 < nI) {
        float4 v = *reinterpret_cast<const float4*>(&Wih[(size_t)i4 * 4]);
        reinterpret_cast<__nv_bfloat162*>(g_Wi)[i4 * 2 + 0] = __floats2bfloat162_rn(v.x, v.y);
        reinterpret_cast<__nv_bfloat162*>(g_Wi)[i4 * 2 + 1] = __floats2bfloat162_rn(v.z, v.w);
    }
}

__global__ void k_setup_state(const float* __restrict__ h0,
                              const float* __restrict__ b_ih, const float* __restrict__ b_hh) {
    int i = blockIdx.x * blockDim.x + threadIdx.x;
    if (i < Bb * Hh) g_h[0][i] = __float2bfloat16(h0[i]);
    if (i < G4)      g_bias[i] = b_ih[i] + b_hh[i];
    if (i < 128)     reinterpret_cast<int*>(g_flag)[i] = 0;
}

// ---------------- helpers ----------------
__device__ __forceinline__ void mma16816(float* d, const uint32_t* a, const uint32_t* b) {
    asm volatile(
        "mma.sync.aligned.m16n8k16.row.col.f32.bf16.bf16.f32 "
        "{%0,%1,%2,%3}, {%4,%5,%6,%7}, {%8,%9}, {%0,%1,%2,%3};\n"
        : "+f"(d[0]), "+f"(d[1]), "+f"(d[2]), "+f"(d[3])
        : "r"(a[0]), "r"(a[1]), "r"(a[2]), "r"(a[3]), "r"(b[0]), "r"(b[1]));
}

#define CP16(dst, src) \
    asm volatile("cp.async.cg.shared.global [%0], [%1], 16;\n" :: "r"(dst), "l"(src))
#define CP_COMMIT() asm volatile("cp.async.commit_group;\n")
#define LDM_X4(r0, r1, r2, r3, addr) \
    asm volatile("ldmatrix.sync.aligned.m8n8.x4.shared.b16 {%0,%1,%2,%3}, [%4];\n" \
                 : "=r"(r0), "=r"(r1), "=r"(r2), "=r"(r3) : "r"(addr))

__device__ __forceinline__ float sigf(float x) {
    return __fdividef(1.0f, 1.0f + __expf(-x));
}
__device__ __forceinline__ float tanhfast(float x) {
    return __fdividef(2.0f, 1.0f + __expf(-2.0f * x)) - 1.0f;
}

// ---------------- Gtab GEMM: Gtab[v][n] = sum_k emb16[v][k] * W_ih[n][k] ----------------
__global__ __launch_bounds__(256) void k_gtab() {
    extern __shared__ __align__(16) char gsm[];
    const uint32_t smb = (uint32_t)__cvta_generic_to_shared(gsm);
    const int tid = threadIdx.x;
    const int lane = tid & 31;
    const int wid = tid >> 5;
    const int n0 = blockIdx.x * 128;
    const int vb = blockIdx.y * 128;

    auto load = [&](int kt) {
#pragma unroll
        for (int i = 0; i < 4; ++i) {
            int id = tid + i * 256;
            int r = id >> 3, c = id & 7;
            int v = vb + r; if (v > VOC - 1) v = VOC - 1;
            uint32_t sw = (uint32_t)(r * 128 + ((c ^ (r & 7)) << 4));
            CP16(smb + (kt % 3) * 16384u + sw, g_emb16 + (size_t)v * Ee + kt * 64 + c * 8);
            CP16(smb + 49152u + (kt % 3) * 16384u + sw, g_Wi + (size_t)(n0 + r) * Ee + kt * 64 + c * 8);
        }
        CP_COMMIT();
    };

    const int mbase = (wid >> 2) * 64;
    const int nbase = (wid & 3) * 32;
    float acc[4][4][4];
#pragma unroll
    for (int mt = 0; mt < 4; ++mt)
#pragma unroll
        for (int nt = 0; nt < 4; ++nt)
#pragma unroll
            for (int e = 0; e < 4; ++e) acc[mt][nt][e] = 0.0f;

    load(0);
    load(1);
    for (int kt = 0; kt < 8; ++kt) {
        if (kt < 7) asm volatile("cp.async.wait_group 1;\n");
        else        asm volatile("cp.async.wait_group 0;\n");
        __syncthreads();
        if (kt + 2 < 8) load(kt + 2);
        const uint32_t ab = smb + (kt % 3) * 16384u;
        const uint32_t bbs = smb + 49152u + (kt % 3) * 16384u;
#pragma unroll
        for (int ks = 0; ks < 64; ks += 16) {
            uint32_t a[4][4];
#pragma unroll
            for (int mt = 0; mt < 4; ++mt) {
                int r = mbase + mt * 16 + (lane & 15);
                int ch = (ks >> 3) + (lane >> 4);
                LDM_X4(a[mt][0], a[mt][1], a[mt][2], a[mt][3],
                       ab + (uint32_t)(r * 128 + ((ch ^ (r & 7)) << 4)));
            }
            uint32_t b[2][4];
#pragma unroll
            for (int bt = 0; bt < 2; ++bt) {
                int gq = lane >> 3;
                int rn = nbase + bt * 16 + ((gq >> 1) << 3) + (lane & 7);
                int ch = (ks >> 3) + (gq & 1);
                LDM_X4(b[bt][0], b[bt][1], b[bt][2], b[bt][3],
                       bbs + (uint32_t)(rn * 128 + ((ch ^ (rn & 7)) << 4)));
            }
#pragma unroll
            for (int mt = 0; mt < 4; ++mt)
#pragma unroll
                for (int nt = 0; nt < 4; ++nt) {
                    uint32_t bf[2] = { b[nt >> 1][(nt & 1) * 2], b[nt >> 1][(nt & 1) * 2 + 1] };
                    mma16816(acc[mt][nt], a[mt], bf);
                }
        }
        __syncthreads();
    }

    const int fr = lane >> 2, fc = (lane & 3) * 2;
#pragma unroll
    for (int mt = 0; mt < 4; ++mt)
#pragma unroll
        for (int nt = 0; nt < 4; ++nt) {
            int c = n0 + nbase + nt * 8 + fc;
            int v0 = vb + mbase + mt * 16 + fr;
            int v1 = v0 + 8;
            if (v0 < VOC)
                *reinterpret_cast<__nv_bfloat162*>(g_gtab + (size_t)v0 * G4 + c) =
                    __floats2bfloat162_rn(acc[mt][nt][0], acc[mt][nt][1]);
            if (v1 < VOC)
                *reinterpret_cast<__nv_bfloat162*>(g_gtab + (size_t)v1 * G4 + c) =
                    __floats2bfloat162_rn(acc[mt][nt][2], acc[mt][nt][3]);
        }
}

// ---------------- persistent fused LSTM (K=1024, Gtab gather epilogue) ----------------
// grid (32, 4). Block tile: gates[64, 128] = h @ Wh_slice^T + Gtab + bias.
// Warps 0-3: mma, warp tile m32 x n64 (2x2). Warps 4-7: cp.async loaders.
// Epilogue: sD staging + 8-warp pointwise, c in regs. Step sync: per-block
// completion flags + one-warp coalesced acquire poll (no global atomics).
__global__ void __launch_bounds__(256, 1)
k_lstm_main(const int* __restrict__ x, const int* __restrict__ x_index,
            const float* __restrict__ c0) {
    extern __shared__ __align__(16) char dynsm[];
    __shared__ float s_bias[128];

    const int tid = threadIdx.x;
    const int lane = tid & 31;
    const int wid = tid >> 5;
    const int gy = blockIdx.y;
    const int bx = blockIdx.x;
    const int b0 = gy * 64;
    const int hc0 = bx * 32;

    const uint32_t smb = (uint32_t)__cvta_generic_to_shared(dynsm);
    const uint32_t Bres = smb;
    const uint32_t Bstr = smb + BSTR_OFF;
    const uint32_t Ab   = smb + A_OFF;
    const uint32_t sGb  = smb + SG_OFF;
    float* sD = reinterpret_cast<float*>(dynsm + BSTR_OFF);   // overlays Bstr (33792B <= 49152B)
    const __nv_bfloat16* sG = reinterpret_cast<const __nv_bfloat16*>(dynsm + SG_OFF);

    if (tid < 128) s_bias[tid] = g_bias[(tid >> 5) * Hh + hc0 + (tid & 31)];

    // ---- resident Wh tiles 0..7 (rows n = gate*32+j over K cols) ----
    for (int i = tid; i < NRES * 1024; i += 256) {
        int kt = i >> 10, rem = i & 1023, n = rem >> 3, c = rem & 7;
        const __nv_bfloat16* src =
            g_Wh + (size_t)((n >> 5) * Hh + hc0 + (n & 31)) * Hh + kt * 64 + c * 8;
        CP16(Bres + (uint32_t)(kt * BTILE + n * 128 + ((c ^ (n & 7)) << 4)), src);
    }
    CP_COMMIT();
    asm volatile("cp.async.wait_group 0;\n");
    __syncthreads();

    // ---- loader assignments (warps 4-7) ----
    const bool loader = (wid >= 4);
    const int l7 = tid & 127;
    const int rb = l7 >> 3;   // 0..15
    const int cc = l7 & 7;
    uint32_t adst[4];
#pragma unroll
    for (int i = 0; i < 4; ++i) {
        int r = rb + 16 * i;
        adst[i] = (uint32_t)(r * 128 + ((cc ^ (r & 7)) << 4));
    }
    uint32_t bdst[8];
#pragma unroll
    for (int i = 0; i < 8; ++i) {
        int r = rb + 16 * i;
        bdst[i] = (uint32_t)(r * 128 + ((cc ^ (r & 7)) << 4));
    }
    const int sg_r = l7 >> 1;          // sG row 0..63
    const int sg_cb = (l7 & 1) * 8;    // chunk base

    // ---- mma warp config (warps 0-3): 2(m) x 2(n), warp tile m32 x n64 ----
    const int mbase = ((wid >> 1) & 1) * 32;
    const int nbase = (wid & 1) * 64;

    // ---- epilogue state: all threads own 8 (bb, jj) items, c in regs ----
    float creg[8];
    int xib[8];
    {
        const int jj = tid & 31;
#pragma unroll
        for (int w = 0; w < 8; ++w) {
            int bb = w * 8 + (tid >> 5);
            int b = b0 + bb;
            xib[w] = x_index[b];
            creg[w] = c0[(size_t)b * Hh + hc0 + jj];
        }
    }

    auto sG_load = [&](int t) {
        if (loader) {
            int tok = x[(size_t)(b0 + sg_r) * Tt + t];
            const __nv_bfloat16* gr = g_gtab + (size_t)tok * G4;
#pragma unroll
            for (int q = 0; q < 8; ++q) {
                int c = sg_cb + q;
                CP16(sGb + (uint32_t)(sg_r * 256 + c * 16), gr + (c >> 2) * Hh + hc0 + (c & 3) * 8);
            }
        }
        CP_COMMIT();
    };

    auto load_tile = [&](int kt, int t) {
        if (loader) {
            const uint32_t st = Ab + (uint32_t)(kt % 3) * ATILE;
            const __nv_bfloat16* hrd = g_h[t & 1];
#pragma unroll
            for (int i = 0; i < 4; ++i)
                CP16(st + adst[i], hrd + (size_t)(b0 + rb + 16 * i) * Hh + kt * 64 + cc * 8);
            if (kt >= NRES) {
                const uint32_t bs = Bstr + (uint32_t)(kt % 3) * BTILE;
#pragma unroll
                for (int i = 0; i < 8; ++i) {
                    int n = rb + 16 * i;
                    const __nv_bfloat16* src =
                        g_Wh + (size_t)((n >> 5) * Hh + hc0 + (n & 31)) * Hh + kt * 64 + cc * 8;
                    CP16(bs + bdst[i], src);
                }
            }
        }
        CP_COMMIT();
    };

    sG_load(0);
    load_tile(0, 0);
    load_tile(1, 0);

    for (int t = 0; t < Tt; ++t) {
        float acc[2][8][4];
#pragma unroll
        for (int mt = 0; mt < 2; ++mt)
#pragma unroll
            for (int nt = 0; nt < 8; ++nt)
#pragma unroll
                for (int e = 0; e < 4; ++e) acc[mt][nt][e] = 0.0f;

        for (int it = 0; it < NT; ++it) {
            if (it < NT - 1) asm volatile("cp.async.wait_group 1;\n");
            else             asm volatile("cp.async.wait_group 0;\n");
            __syncthreads();
            if (it + 2 < NT) load_tile(it + 2, t);

            if (wid < 4) {
                const uint32_t ab = Ab + (uint32_t)(it % 3) * ATILE;
                const uint32_t bb = (it < NRES) ? (Bres + (uint32_t)it * BTILE)
                                                : (Bstr + (uint32_t)(it % 3) * BTILE);
#pragma unroll
                for (int ks = 0; ks < 64; ks += 16) {
                    uint32_t a[2][4];
#pragma unroll
                    for (int mt = 0; mt < 2; ++mt) {
                        int r = mbase + mt * 16 + (lane & 15);
                        int ch = (ks >> 3) + (lane >> 4);
                        LDM_X4(a[mt][0], a[mt][1], a[mt][2], a[mt][3],
                               ab + (uint32_t)(r * 128 + ((ch ^ (r & 7)) << 4)));
                    }
                    uint32_t b[4][4];
#pragma unroll
                    for (int bt = 0; bt < 4; ++bt) {
                        int gq = lane >> 3;
                        int rn = nbase + bt * 16 + ((gq >> 1) << 3) + (lane & 7);
                        int ch = (ks >> 3) + (gq & 1);
                        LDM_X4(b[bt][0], b[bt][1], b[bt][2], b[bt][3],
                               bb + (uint32_t)(rn * 128 + ((ch ^ (rn & 7)) << 4)));
                    }
#pragma unroll
                    for (int mt = 0; mt < 2; ++mt)
#pragma unroll
                        for (int nt = 0; nt < 8; ++nt) {
                            uint32_t bf[2] = { b[nt >> 1][(nt & 1) * 2], b[nt >> 1][(nt & 1) * 2 + 1] };
                            mma16816(acc[mt][nt], a[mt], bf);
                        }
                }
            }
        }
        __syncthreads();   // mma done; Bstr stages reusable as sD

        // ---- stage D: sD[m][n], rows padded to 132 floats (overlays Bstr) ----
        if (wid < 4) {
            const int fr = lane >> 2, fc = (lane & 3) * 2;
#pragma unroll
            for (int mt = 0; mt < 2; ++mt)
#pragma unroll
                for (int nt = 0; nt < 8; ++nt) {
                    int m = mbase + mt * 16 + fr;
                    int n = nbase + nt * 8 + fc;
                    sD[m * 132 + n]           = acc[mt][nt][0];
                    sD[m * 132 + n + 1]       = acc[mt][nt][1];
                    sD[(m + 8) * 132 + n]     = acc[mt][nt][2];
                    sD[(m + 8) * 132 + n + 1] = acc[mt][nt][3];
                }
        }
        __syncthreads();

        // ---- pointwise LSTM update: all 8 warps, 2048 items ----
        {
            const int jj = tid & 31;
            __nv_bfloat16* hwr = g_h[(t + 1) & 1];
#pragma unroll
            for (int w = 0; w < 8; ++w) {
                int bb = w * 8 + (tid >> 5);
                int b = b0 + bb;
                const float* row = sD + bb * 132;
                const __nv_bfloat16* grow = sG + bb * 128;
                float ig = row[jj]      + __bfloat162float(grow[jj])      + s_bias[jj];
                float fg = row[32 + jj] + __bfloat162float(grow[32 + jj]) + s_bias[32 + jj];
                float gg = row[64 + jj] + __bfloat162float(grow[64 + jj]) + s_bias[64 + jj];
                float og = row[96 + jj] + __bfloat162float(grow[96 + jj]) + s_bias[96 + jj];
                float cv = sigf(fg) * creg[w] + sigf(ig) * tanhfast(gg);
                creg[w] = cv;
                float hv = sigf(og) * tanhfast(cv);
                hwr[(size_t)b * Hh + hc0 + jj] = __float2bfloat16(hv);
                if (xib[w] == t) g_hn[(size_t)b * Hh + hc0 + jj] = hv;
            }
        }
        __syncthreads();   // h(t+1) slice written; sG buffer free

        if (t + 1 < Tt) {
            // publish completion (proven R9 store pattern), earliest possible
            if (tid == 0) {
                asm volatile("membar.gl;" ::: "memory");
                asm volatile("st.relaxed.gpu.global.u32 [%0], %1;"
                             :: "l"(&g_flag[gy][bx]), "r"(t + 1) : "memory");
            }
            sG_load(t + 1);   // token-only dependence; overlaps the poll below
            // one-warp coalesced poll of all 32 producer flags (replaces atomic barrier)
            if (wid == 4) {
                const int* fp = &g_flag[gy][lane];
                int v;
                do {
                    asm volatile("ld.acquire.gpu.u32 %0, [%1];" : "=r"(v) : "l"(fp) : "memory");
                } while (__any_sync(0xffffffffu, v <= t));
            }
            __syncthreads();
            load_tile(0, t + 1);
            load_tile(1, t + 1);
        }
    }
}

// ---------------- fc1: z = tanh(hn @ fc1_w^T + fc1_b), fp32 ----------------
__global__ __launch_bounds__(256) void k_fc1(const float* __restrict__ fc1_w,
                                             const float* __restrict__ fc1_b) {
    __shared__ float sA[16][68];
    __shared__ float sB[16][68];
    const int tid = threadIdx.x;
    const int b0 = blockIdx.y * 64;
    const int n0 = blockIdx.x * 64;
    const int tx = tid & 15, ty = tid >> 4;
    const int lr = tid & 63;
    const int lc4 = (tid >> 6) * 4;

    float acc[4][4];
#pragma unroll
    for (int i = 0; i < 4; ++i)
#pragma unroll
        for (int jn = 0; jn < 4; ++jn) acc[i][jn] = 0.0f;

    for (int k0 = 0; k0 < Hh; k0 += 16) {
        float4 va = *reinterpret_cast<const float4*>(&g_hn[(size_t)(b0 + lr) * Hh + k0 + lc4]);
        float4 vb = *reinterpret_cast<const float4*>(&fc1_w[(size_t)(n0 + lr) * Hh + k0 + lc4]);
        __syncthreads();
        sA[lc4 + 0][lr] = va.x; sA[lc4 + 1][lr] = va.y; sA[lc4 + 2][lr] = va.z; sA[lc4 + 3][lr] = va.w;
        sB[lc4 + 0][lr] = vb.x; sB[lc4 + 1][lr] = vb.y; sB[lc4 + 2][lr] = vb.z; sB[lc4 + 3][lr] = vb.w;
        __syncthreads();
#pragma unroll
        for (int k = 0; k < 16; ++k) {
            float4 ra4 = *reinterpret_cast<const float4*>(&sA[k][ty * 4]);
            float4 rb4 = *reinterpret_cast<const float4*>(&sB[k][tx * 4]);
            float ra[4] = {ra4.x, ra4.y, ra4.z, ra4.w};
            float rb[4] = {rb4.x, rb4.y, rb4.z, rb4.w};
#pragma unroll
            for (int i = 0; i < 4; ++i)
#pragma unroll
                for (int jn = 0; jn < 4; ++jn) acc[i][jn] += ra[i] * rb[jn];
        }
    }
#pragma unroll
    for (int i = 0; i < 4; ++i)
#pragma unroll
        for (int jn = 0; jn < 4; ++jn) {
            int bb = b0 + ty * 4 + i;
            int nn = n0 + tx * 4 + jn;
            g_z[(size_t)bb * Mm + nn] = tanhf(acc[i][jn] + fc1_b[nn]);
        }
}

// ---------------- fc2 + log_softmax (O=2) ----------------
__global__ __launch_bounds__(128) void k_fc2(const float* __restrict__ fc2_w,
                                             const float* __restrict__ fc2_b,
                                             float* __restrict__ out) {
    const int b = blockIdx.x;
    const int tid = threadIdx.x;
    float p0 = 0.f, p1 = 0.f;
    for (int k = tid; k < Mm; k += 128) {
        float zv = g_z[(size_t)b * Mm + k];
        p0 += zv * fc2_w[k];
        p1 += zv * fc2_w[Mm + k];
    }
#pragma unroll
    for (int off = 16; off; off >>= 1) {
        p0 += __shfl_down_sync(0xffffffffu, p0, off);
        p1 += __shfl_down_sync(0xffffffffu, p1, off);
    }
    __shared__ float s0[4], s1[4];
    if ((tid & 31) == 0) { s0[tid >> 5] = p0; s1[tid >> 5] = p1; }
    __syncthreads();
    if (tid == 0) {
        float l0 = s0[0] + s0[1] + s0[2] + s0[3] + fc2_b[0];
        float l1 = s1[0] + s1[1] + s1[2] + s1[3] + fc2_b[1];
        float mx = fmaxf(l0, l1);
        float lse = mx + logf(expf(l0 - mx) + expf(l1 - mx));
        out[b * 2 + 0] = l0 - lse;
        out[b * 2 + 1] = l1 - lse;
    }
}

// ---------------- launch ----------------
extern "C" void kernel_launch(void* const* d_in, const int* in_sizes, int n_in,
                              void* d_out, int out_size) {
    const int*   x       = (const int*)d_in[0];
    const int*   x_index = (const int*)d_in[1];
    const float* emb     = (const float*)d_in[2];
    const float* W_ih    = (const float*)d_in[3];
    const float* W_hh    = (const float*)d_in[4];
    const float* b_ih    = (const float*)d_in[5];
    const float* b_hh    = (const float*)d_in[6];
    const float* fc1_w   = (const float*)d_in[7];
    const float* fc1_b   = (const float*)d_in[8];
    const float* fc2_w   = (const float*)d_in[9];
    const float* fc2_b   = (const float*)d_in[10];
    const float* h0      = (const float*)d_in[11];
    const float* c0      = (const float*)d_in[12];
    float* out = (float*)d_out;

    (void)in_sizes; (void)n_in; (void)out_size;

    cudaFuncSetAttribute(k_lstm_main, cudaFuncAttributeMaxDynamicSharedMemorySize, DYN_SMEM);
    cudaFuncSetAttribute(k_gtab, cudaFuncAttributeMaxDynamicSharedMemorySize, GT_DYN);

    k_setup_emb<<<(VOC * Ee / 4 + 255) / 256, 256>>>(emb);
    k_setup_w<<<(G4 * Hh / 4 + 255) / 256, 256>>>(W_ih, W_hh);
    k_setup_state<<<(Bb * Hh + 255) / 256, 256>>>(h0, b_ih, b_hh);

    k_gtab<<<dim3(G4 / 128, (VOC + 127) / 128), 256, GT_DYN>>>();

    k_lstm_main<<<dim3(GX, GY), 256, DYN_SMEM>>>(x, x_index, c0);

    k_fc1<<<dim3(Mm / 64, Bb / 64), 256>>>(fc1_w, fc1_b);
    k_fc2<<<Bb, 128>>>(fc2_w, fc2_b, out);
}

// round 11
// speedup vs baseline: 1.7197x; 1.1634x over previous
#include <cuda_runtime.h>
#include <cuda_bf16.h>
#include <stdint.h>

#define Bb 256
#define Tt 512
#define Ee 512
#define Hh 1024
#define G4 4096
#define Mm 1024
#define VOC 32001

#define GX 32              // n-tiles (32 h-cols -> N=128 with 4 gates)
#define GY 4               // batch groups (64 each -> M=64)
#define GRPBLK GX
#define NT 16              // K-tiles of 64 over K=1024 (h only)
#define NRES 8             // resident W_hh K-tiles; 8..15 streamed
#define BTILE 16384        // 128 rows x 128B
#define ATILE 8192         // 64 rows x 128B
#define BSTR_OFF (NRES * BTILE)          // 131072
#define A_OFF    (BSTR_OFF + 3 * BTILE)  // 180224
#define SG_OFF   (A_OFF + 3 * ATILE)     // 204800
#define DYN_SMEM (SG_OFF + 16384)        // 221184
#define GT_DYN   98304                   // k_gtab: 3 stages x (16K A + 16K B)

// ---------------- static device scratch ----------------
__device__ __align__(16) __nv_bfloat16 g_emb16[(size_t)VOC * Ee];      // 32.8 MB
__device__ __align__(16) __nv_bfloat16 g_Wi[(size_t)G4 * Ee];          // 4.2 MB
__device__ __align__(16) __nv_bfloat16 g_Wh[(size_t)G4 * Hh];          // 8.4 MB
__device__ __align__(16) __nv_bfloat16 g_gtab[(size_t)VOC * G4];       // 262 MB: Gtab[v] = W_ih @ emb[v]
__device__ float         g_bias[G4];
__device__ __align__(16) __nv_bfloat16 g_h[2][Bb * Hh];                // double buffered (full barrier/step)
__device__ float         g_hn[Bb * Hh];
__device__ float         g_z[Bb * Mm];
__device__ unsigned      g_bar4[4];                                    // per-gy full barrier
__device__ unsigned      g_pair[4][16];                                // per-gy pair counters

// ---------------- setup kernels ----------------
__global__ void k_setup_emb(const float* __restrict__ emb) {
    int i4 = blockIdx.x * blockDim.x + threadIdx.x;
    const int n4 = (VOC * Ee) / 4;
    if (i4 >= n4) return;
    float4 v = reinterpret_cast<const float4*>(emb)[i4];
    reinterpret_cast<__nv_bfloat162*>(g_emb16)[i4 * 2 + 0] = __floats2bfloat162_rn(v.x, v.y);
    reinterpret_cast<__nv_bfloat162*>(g_emb16)[i4 * 2 + 1] = __floats2bfloat162_rn(v.z, v.w);
}

__global__ void k_setup_w(const float* __restrict__ Wih, const float* __restrict__ Whh) {
    int i4 = blockIdx.x * blockDim.x + threadIdx.x;
    const int nW = (G4 * Hh) / 4;
    if (i4 < nW) {
        float4 v = *reinterpret_cast<const float4*>(&Whh[(size_t)i4 * 4]);
        reinterpret_cast<__nv_bfloat162*>(g_Wh)[i4 * 2 + 0] = __floats2bfloat162_rn(v.x, v.y);
        reinterpret_cast<__nv_bfloat162*>(g_Wh)[i4 * 2 + 1] = __floats2bfloat162_rn(v.z, v.w);
    }
    const int nI = (G4 * Ee) / 4;
    if (i4 < nI) {
        float4 v = *reinterpret_cast<const float4*>(&Wih[(size_t)i4 * 4]);
        reinterpret_cast<__nv_bfloat162*>(g_Wi)[i4 * 2 + 0] = __floats2bfloat162_rn(v.x, v.y);
        reinterpret_cast<__nv_bfloat162*>(g_Wi)[i4 * 2 + 1] = __floats2bfloat162_rn(v.z, v.w);
    }
}

__global__ void k_setup_state(const float* __restrict__ h0,
                              const float* __restrict__ b_ih, const float* __restrict__ b_hh) {
    int i = blockIdx.x * blockDim.x + threadIdx.x;
    if (i < Bb * Hh) g_h[0][i] = __float2bfloat16(h0[i]);
    if (i < G4)      g_bias[i] = b_ih[i] + b_hh[i];
    if (i < 4)       g_bar4[i] = 0u;
    if (i < 64)      reinterpret_cast<unsigned*>(g_pair)[i] = 0u;
}

// ---------------- helpers ----------------
__device__ __forceinline__ void mma16816(float* d, const uint32_t* a, const uint32_t* b) {
    asm volatile(
        "mma.sync.aligned.m16n8k16.row.col.f32.bf16.bf16.f32 "
        "{%0,%1,%2,%3}, {%4,%5,%6,%7}, {%8,%9}, {%0,%1,%2,%3};\n"
        : "+f"(d[0]), "+f"(d[1]), "+f"(d[2]), "+f"(d[3])
        : "r"(a[0]), "r"(a[1]), "r"(a[2]), "r"(a[3]), "r"(b[0]), "r"(b[1]));
}

#define CP16(dst, src) \
    asm volatile("cp.async.cg.shared.global [%0], [%1], 16;\n" :: "r"(dst), "l"(src))
#define CP_COMMIT() asm volatile("cp.async.commit_group;\n")
#define LDM_X4(r0, r1, r2, r3, addr) \
    asm volatile("ldmatrix.sync.aligned.m8n8.x4.shared.b16 {%0,%1,%2,%3}, [%4];\n" \
                 : "=r"(r0), "=r"(r1), "=r"(r2), "=r"(r3) : "r"(addr))

__device__ __forceinline__ float sigf(float x) {
    return __fdividef(1.0f, 1.0f + __expf(-x));
}
__device__ __forceinline__ float tanhfast(float x) {
    return __fdividef(2.0f, 1.0f + __expf(-2.0f * x)) - 1.0f;
}

// ---------------- Gtab GEMM: Gtab[v][n] = sum_k emb16[v][k] * W_ih[n][k] ----------------
__global__ __launch_bounds__(256) void k_gtab() {
    extern __shared__ __align__(16) char gsm[];
    const uint32_t smb = (uint32_t)__cvta_generic_to_shared(gsm);
    const int tid = threadIdx.x;
    const int lane = tid & 31;
    const int wid = tid >> 5;
    const int n0 = blockIdx.x * 128;
    const int vb = blockIdx.y * 128;

    auto load = [&](int kt) {
#pragma unroll
        for (int i = 0; i < 4; ++i) {
            int id = tid + i * 256;
            int r = id >> 3, c = id & 7;
            int v = vb + r; if (v > VOC - 1) v = VOC - 1;
            uint32_t sw = (uint32_t)(r * 128 + ((c ^ (r & 7)) << 4));
            CP16(smb + (kt % 3) * 16384u + sw, g_emb16 + (size_t)v * Ee + kt * 64 + c * 8);
            CP16(smb + 49152u + (kt % 3) * 16384u + sw, g_Wi + (size_t)(n0 + r) * Ee + kt * 64 + c * 8);
        }
        CP_COMMIT();
    };

    const int mbase = (wid >> 2) * 64;
    const int nbase = (wid & 3) * 32;
    float acc[4][4][4];
#pragma unroll
    for (int mt = 0; mt < 4; ++mt)
#pragma unroll
        for (int nt = 0; nt < 4; ++nt)
#pragma unroll
            for (int e = 0; e < 4; ++e) acc[mt][nt][e] = 0.0f;

    load(0);
    load(1);
    for (int kt = 0; kt < 8; ++kt) {
        if (kt < 7) asm volatile("cp.async.wait_group 1;\n");
        else        asm volatile("cp.async.wait_group 0;\n");
        __syncthreads();
        if (kt + 2 < 8) load(kt + 2);
        const uint32_t ab = smb + (kt % 3) * 16384u;
        const uint32_t bbs = smb + 49152u + (kt % 3) * 16384u;
#pragma unroll
        for (int ks = 0; ks < 64; ks += 16) {
            uint32_t a[4][4];
#pragma unroll
            for (int mt = 0; mt < 4; ++mt) {
                int r = mbase + mt * 16 + (lane & 15);
                int ch = (ks >> 3) + (lane >> 4);
                LDM_X4(a[mt][0], a[mt][1], a[mt][2], a[mt][3],
                       ab + (uint32_t)(r * 128 + ((ch ^ (r & 7)) << 4)));
            }
            uint32_t b[2][4];
#pragma unroll
            for (int bt = 0; bt < 2; ++bt) {
                int gq = lane >> 3;
                int rn = nbase + bt * 16 + ((gq >> 1) << 3) + (lane & 7);
                int ch = (ks >> 3) + (gq & 1);
                LDM_X4(b[bt][0], b[bt][1], b[bt][2], b[bt][3],
                       bbs + (uint32_t)(rn * 128 + ((ch ^ (rn & 7)) << 4)));
            }
#pragma unroll
            for (int mt = 0; mt < 4; ++mt)
#pragma unroll
                for (int nt = 0; nt < 4; ++nt) {
                    uint32_t bf[2] = { b[nt >> 1][(nt & 1) * 2], b[nt >> 1][(nt & 1) * 2 + 1] };
                    mma16816(acc[mt][nt], a[mt], bf);
                }
        }
        __syncthreads();
    }

    const int fr = lane >> 2, fc = (lane & 3) * 2;
#pragma unroll
    for (int mt = 0; mt < 4; ++mt)
#pragma unroll
        for (int nt = 0; nt < 4; ++nt) {
            int c = n0 + nbase + nt * 8 + fc;
            int v0 = vb + mbase + mt * 16 + fr;
            int v1 = v0 + 8;
            if (v0 < VOC)
                *reinterpret_cast<__nv_bfloat162*>(g_gtab + (size_t)v0 * G4 + c) =
                    __floats2bfloat162_rn(acc[mt][nt][0], acc[mt][nt][1]);
            if (v1 < VOC)
                *reinterpret_cast<__nv_bfloat162*>(g_gtab + (size_t)v1 * G4 + c) =
                    __floats2bfloat162_rn(acc[mt][nt][2], acc[mt][nt][3]);
        }
}

// ---------------- persistent fused LSTM (K=1024, Gtab gather epilogue) ----------------
// grid (32, 4). Block tile: gates[64, 128] = h @ Wh_slice^T + Gtab + bias.
// Warps 0-3: mma m32n64 (2x2). Warps 4-7: cp.async loaders.
// K-tile ROTATION: block bx consumes kt = (bx/2 + i) mod 16, so its first tile
// needs only its pair's h columns -> pair handshake lets tile i0 of step t+1
// prefetch UNDER the full group barrier. Everything else identical to R8.
__global__ void __launch_bounds__(256, 1)
k_lstm_main(const int* __restrict__ x, const int* __restrict__ x_index,
            const float* __restrict__ c0) {
    extern __shared__ __align__(16) char dynsm[];
    __shared__ float s_bias[128];

    const int tid = threadIdx.x;
    const int lane = tid & 31;
    const int wid = tid >> 5;
    const int gy = blockIdx.y;
    const int bx = blockIdx.x;
    const int b0 = gy * 64;
    const int hc0 = bx * 32;
    const int kt0 = bx >> 1;      // rotation base: own/pair columns first

    const uint32_t smb = (uint32_t)__cvta_generic_to_shared(dynsm);
    const uint32_t Bres = smb;
    const uint32_t Bstr = smb + BSTR_OFF;
    const uint32_t Ab   = smb + A_OFF;
    const uint32_t sGb  = smb + SG_OFF;
    float* sD = reinterpret_cast<float*>(dynsm + BSTR_OFF);   // overlays Bstr (33792B <= 49152B)
    const __nv_bfloat16* sG = reinterpret_cast<const __nv_bfloat16*>(dynsm + SG_OFF);

    if (tid < 128) s_bias[tid] = g_bias[(tid >> 5) * Hh + hc0 + (tid & 31)];

    // ---- resident Wh tiles 0..7 (rows n = gate*32+j over K cols) ----
    for (int i = tid; i < NRES * 1024; i += 256) {
        int kt = i >> 10, rem = i & 1023, n = rem >> 3, c = rem & 7;
        const __nv_bfloat16* src =
            g_Wh + (size_t)((n >> 5) * Hh + hc0 + (n & 31)) * Hh + kt * 64 + c * 8;
        CP16(Bres + (uint32_t)(kt * BTILE + n * 128 + ((c ^ (n & 7)) << 4)), src);
    }
    CP_COMMIT();
    asm volatile("cp.async.wait_group 0;\n");
    __syncthreads();

    // ---- loader assignments (warps 4-7) ----
    const bool loader = (wid >= 4);
    const int l7 = tid & 127;
    const int rb = l7 >> 3;   // 0..15
    const int cc = l7 & 7;
    uint32_t adst[4];
#pragma unroll
    for (int i = 0; i < 4; ++i) {
        int r = rb + 16 * i;
        adst[i] = (uint32_t)(r * 128 + ((cc ^ (r & 7)) << 4));
    }
    uint32_t bdst[8];
#pragma unroll
    for (int i = 0; i < 8; ++i) {
        int r = rb + 16 * i;
        bdst[i] = (uint32_t)(r * 128 + ((cc ^ (r & 7)) << 4));
    }
    const int sg_r = l7 >> 1;          // sG row 0..63
    const int sg_cb = (l7 & 1) * 8;    // chunk base

    // ---- mma warp config (warps 0-3): 2(m) x 2(n), warp tile m32 x n64 ----
    const int mbase = ((wid >> 1) & 1) * 32;
    const int nbase = (wid & 1) * 64;

    // ---- epilogue state: all threads own 8 (bb, jj) items, c in regs ----
    float creg[8];
    int xib[8];
    {
        const int jj = tid & 31;
#pragma unroll
        for (int w = 0; w < 8; ++w) {
            int bb = w * 8 + (tid >> 5);
            int b = b0 + bb;
            xib[w] = x_index[b];
            creg[w] = c0[(size_t)b * Hh + hc0 + jj];
        }
    }

    auto sG_load = [&](int t) {
        if (loader) {
            int tok = x[(size_t)(b0 + sg_r) * Tt + t];
            const __nv_bfloat16* gr = g_gtab + (size_t)tok * G4;
#pragma unroll
            for (int q = 0; q < 8; ++q) {
                int c = sg_cb + q;
                CP16(sGb + (uint32_t)(sg_r * 256 + c * 16), gr + (c >> 2) * Hh + hc0 + (c & 3) * 8);
            }
        }
        CP_COMMIT();
    };

    // load rotated tile i (kt = (kt0+i)&15) of step t into stage i%3
    auto load_tile = [&](int i, int t) {
        if (loader) {
            const int kt = (kt0 + i) & 15;
            const uint32_t st = Ab + (uint32_t)(i % 3) * ATILE;
            const __nv_bfloat16* hrd = g_h[t & 1];
#pragma unroll
            for (int q = 0; q < 4; ++q)
                CP16(st + adst[q], hrd + (size_t)(b0 + rb + 16 * q) * Hh + kt * 64 + cc * 8);
            if (kt >= NRES) {
                const uint32_t bs = Bstr + (uint32_t)(i % 3) * BTILE;
#pragma unroll
                for (int q = 0; q < 8; ++q) {
                    int n = rb + 16 * q;
                    const __nv_bfloat16* src =
                        g_Wh + (size_t)((n >> 5) * Hh + hc0 + (n & 31)) * Hh + kt * 64 + cc * 8;
                    CP16(bs + bdst[q], src);
                }
            }
        }
        CP_COMMIT();
    };

    sG_load(0);
    load_tile(0, 0);
    load_tile(1, 0);

    for (int t = 0; t < Tt; ++t) {
        float acc[2][8][4];
#pragma unroll
        for (int mt = 0; mt < 2; ++mt)
#pragma unroll
            for (int nt = 0; nt < 8; ++nt)
#pragma unroll
                for (int e = 0; e < 4; ++e) acc[mt][nt][e] = 0.0f;

        for (int it = 0; it < NT; ++it) {
            if (it < NT - 1) asm volatile("cp.async.wait_group 1;\n");
            else             asm volatile("cp.async.wait_group 0;\n");
            __syncthreads();
            if (it + 2 < NT) load_tile(it + 2, t);

            if (wid < 4) {
                const int kt = (kt0 + it) & 15;
                const uint32_t ab = Ab + (uint32_t)(it % 3) * ATILE;
                const uint32_t bb = (kt < NRES) ? (Bres + (uint32_t)kt * BTILE)
                                                : (Bstr + (uint32_t)(it % 3) * BTILE);
#pragma unroll
                for (int ks = 0; ks < 64; ks += 16) {
                    uint32_t a[2][4];
#pragma unroll
                    for (int mt = 0; mt < 2; ++mt) {
                        int r = mbase + mt * 16 + (lane & 15);
                        int ch = (ks >> 3) + (lane >> 4);
                        LDM_X4(a[mt][0], a[mt][1], a[mt][2], a[mt][3],
                               ab + (uint32_t)(r * 128 + ((ch ^ (r & 7)) << 4)));
                    }
                    uint32_t b[4][4];
#pragma unroll
                    for (int bt = 0; bt < 4; ++bt) {
                        int gq = lane >> 3;
                        int rn = nbase + bt * 16 + ((gq >> 1) << 3) + (lane & 7);
                        int ch = (ks >> 3) + (gq & 1);
                        LDM_X4(b[bt][0], b[bt][1], b[bt][2], b[bt][3],
                               bb + (uint32_t)(rn * 128 + ((ch ^ (rn & 7)) << 4)));
                    }
#pragma unroll
                    for (int mt = 0; mt < 2; ++mt)
#pragma unroll
                        for (int nt = 0; nt < 8; ++nt) {
                            uint32_t bf[2] = { b[nt >> 1][(nt & 1) * 2], b[nt >> 1][(nt & 1) * 2 + 1] };
                            mma16816(acc[mt][nt], a[mt], bf);
                        }
                }
            }
        }
        __syncthreads();   // mma done; Bstr stages reusable as sD

        // ---- stage D: sD[m][n], rows padded to 132 floats (overlays Bstr) ----
        if (wid < 4) {
            const int fr = lane >> 2, fc = (lane & 3) * 2;
#pragma unroll
            for (int mt = 0; mt < 2; ++mt)
#pragma unroll
                for (int nt = 0; nt < 8; ++nt) {
                    int m = mbase + mt * 16 + fr;
                    int n = nbase + nt * 8 + fc;
                    sD[m * 132 + n]           = acc[mt][nt][0];
                    sD[m * 132 + n + 1]       = acc[mt][nt][1];
                    sD[(m + 8) * 132 + n]     = acc[mt][nt][2];
                    sD[(m + 8) * 132 + n + 1] = acc[mt][nt][3];
                }
        }
        __syncthreads();

        // ---- pointwise LSTM update: all 8 warps, 2048 items ----
        {
            const int jj = tid & 31;
            __nv_bfloat16* hwr = g_h[(t + 1) & 1];
#pragma unroll
            for (int w = 0; w < 8; ++w) {
                int bb = w * 8 + (tid >> 5);
                int b = b0 + bb;
                const float* row = sD + bb * 132;
                const __nv_bfloat16* grow = sG + bb * 128;
                float ig = row[jj]      + __bfloat162float(grow[jj])      + s_bias[jj];
                float fg = row[32 + jj] + __bfloat162float(grow[32 + jj]) + s_bias[32 + jj];
                float gg = row[64 + jj] + __bfloat162float(grow[64 + jj]) + s_bias[64 + jj];
                float og = row[96 + jj] + __bfloat162float(grow[96 + jj]) + s_bias[96 + jj];
                float cv = sigf(fg) * creg[w] + sigf(ig) * tanhfast(gg);
                creg[w] = cv;
                float hv = sigf(og) * tanhfast(cv);
                hwr[(size_t)b * Hh + hc0 + jj] = __float2bfloat16(hv);
                if (xib[w] == t) g_hn[(size_t)b * Hh + hc0 + jj] = hv;
            }
        }
        __syncthreads();   // h(t+1) slice written; sG buffer free

        if (t + 1 < Tt) {
            // publish: pair counter (gates tile i0) + group counter (gates tile i1+)
            if (tid == 0) {
                asm volatile("red.release.gpu.global.add.u32 [%0], %1;"
                             :: "l"(&g_pair[gy][kt0]), "r"(1u) : "memory");
                asm volatile("red.release.gpu.global.add.u32 [%0], %1;"
                             :: "l"(&g_bar4[gy]), "r"(1u) : "memory");
            }
            sG_load(t + 1);   // token-only dependence
            // pair handshake -> prefetch tile i0 UNDER the group barrier
            if (tid == 128) {
                unsigned target = 2u * (unsigned)(t + 1);
                const unsigned* pp = &g_pair[gy][kt0];
                unsigned v;
                do {
                    asm volatile("ld.acquire.gpu.global.u32 %0, [%1];" : "=r"(v) : "l"(pp) : "memory");
                } while (v < target);
            }
            if (loader) asm volatile("bar.sync 2, 128;" ::: "memory");
            load_tile(0, t + 1);
            // full group barrier (R8-proven mechanism)
            if (tid == 0) {
                unsigned* bar = &g_bar4[gy];
                unsigned target = (unsigned)(t + 1) * GRPBLK;
                unsigned v;
                do {
                    asm volatile("ld.acquire.gpu.global.u32 %0, [%1];" : "=r"(v) : "l"(bar) : "memory");
                } while (v < target);
            }
            __syncthreads();
            load_tile(1, t + 1);
        }
    }
}

// ---------------- fc1: z = tanh(hn @ fc1_w^T + fc1_b), fp32 ----------------
__global__ __launch_bounds__(256) void k_fc1(const float* __restrict__ fc1_w,
                                             const float* __restrict__ fc1_b) {
    __shared__ float sA[16][68];
    __shared__ float sB[16][68];
    const int tid = threadIdx.x;
    const int b0 = blockIdx.y * 64;
    const int n0 = blockIdx.x * 64;
    const int tx = tid & 15, ty = tid >> 4;
    const int lr = tid & 63;
    const int lc4 = (tid >> 6) * 4;

    float acc[4][4];
#pragma unroll
    for (int i = 0; i < 4; ++i)
#pragma unroll
        for (int jn = 0; jn < 4; ++jn) acc[i][jn] = 0.0f;

    for (int k0 = 0; k0 < Hh; k0 += 16) {
        float4 va = *reinterpret_cast<const float4*>(&g_hn[(size_t)(b0 + lr) * Hh + k0 + lc4]);
        float4 vb = *reinterpret_cast<const float4*>(&fc1_w[(size_t)(n0 + lr) * Hh + k0 + lc4]);
        __syncthreads();
        sA[lc4 + 0][lr] = va.x; sA[lc4 + 1][lr] = va.y; sA[lc4 + 2][lr] = va.z; sA[lc4 + 3][lr] = va.w;
        sB[lc4 + 0][lr] = vb.x; sB[lc4 + 1][lr] = vb.y; sB[lc4 + 2][lr] = vb.z; sB[lc4 + 3][lr] = vb.w;
        __syncthreads();
#pragma unroll
        for (int k = 0; k < 16; ++k) {
            float4 ra4 = *reinterpret_cast<const float4*>(&sA[k][ty * 4]);
            float4 rb4 = *reinterpret_cast<const float4*>(&sB[k][tx * 4]);
            float ra[4] = {ra4.x, ra4.y, ra4.z, ra4.w};
            float rb[4] = {rb4.x, rb4.y, rb4.z, rb4.w};
#pragma unroll
            for (int i = 0; i < 4; ++i)
#pragma unroll
                for (int jn = 0; jn < 4; ++jn) acc[i][jn] += ra[i] * rb[jn];
        }
    }
#pragma unroll
    for (int i = 0; i < 4; ++i)
#pragma unroll
        for (int jn = 0; jn < 4; ++jn) {
            int bb = b0 + ty * 4 + i;
            int nn = n0 + tx * 4 + jn;
            g_z[(size_t)bb * Mm + nn] = tanhf(acc[i][jn] + fc1_b[nn]);
        }
}

// ---------------- fc2 + log_softmax (O=2) ----------------
__global__ __launch_bounds__(128) void k_fc2(const float* __restrict__ fc2_w,
                                             const float* __restrict__ fc2_b,
                                             float* __restrict__ out) {
    const int b = blockIdx.x;
    const int tid = threadIdx.x;
    float p0 = 0.f, p1 = 0.f;
    for (int k = tid; k < Mm; k += 128) {
        float zv = g_z[(size_t)b * Mm + k];
        p0 += zv * fc2_w[k];
        p1 += zv * fc2_w[Mm + k];
    }
#pragma unroll
    for (int off = 16; off; off >>= 1) {
        p0 += __shfl_down_sync(0xffffffffu, p0, off);
        p1 += __shfl_down_sync(0xffffffffu, p1, off);
    }
    __shared__ float s0[4], s1[4];
    if ((tid & 31) == 0) { s0[tid >> 5] = p0; s1[tid >> 5] = p1; }
    __syncthreads();
    if (tid == 0) {
        float l0 = s0[0] + s0[1] + s0[2] + s0[3] + fc2_b[0];
        float l1 = s1[0] + s1[1] + s1[2] + s1[3] + fc2_b[1];
        float mx = fmaxf(l0, l1);
        float lse = mx + logf(expf(l0 - mx) + expf(l1 - mx));
        out[b * 2 + 0] = l0 - lse;
        out[b * 2 + 1] = l1 - lse;
    }
}

// ---------------- launch ----------------
extern "C" void kernel_launch(void* const* d_in, const int* in_sizes, int n_in,
                              void* d_out, int out_size) {
    const int*   x       = (const int*)d_in[0];
    const int*   x_index = (const int*)d_in[1];
    const float* emb     = (const float*)d_in[2];
    const float* W_ih    = (const float*)d_in[3];
    const float* W_hh    = (const float*)d_in[4];
    const float* b_ih    = (const float*)d_in[5];
    const float* b_hh    = (const float*)d_in[6];
    const float* fc1_w   = (const float*)d_in[7];
    const float* fc1_b   = (const float*)d_in[8];
    const float* fc2_w   = (const float*)d_in[9];
    const float* fc2_b   = (const float*)d_in[10];
    const float* h0      = (const float*)d_in[11];
    const float* c0      = (const float*)d_in[12];
    float* out = (float*)d_out;

    (void)in_sizes; (void)n_in; (void)out_size;

    cudaFuncSetAttribute(k_lstm_main, cudaFuncAttributeMaxDynamicSharedMemorySize, DYN_SMEM);
    cudaFuncSetAttribute(k_gtab, cudaFuncAttributeMaxDynamicSharedMemorySize, GT_DYN);

    k_setup_emb<<<(VOC * Ee / 4 + 255) / 256, 256>>>(emb);
    k_setup_w<<<(G4 * Hh / 4 + 255) / 256, 256>>>(W_ih, W_hh);
    k_setup_state<<<(Bb * Hh + 255) / 256, 256>>>(h0, b_ih, b_hh);

    k_gtab<<<dim3(G4 / 128, (VOC + 127) / 128), 256, GT_DYN>>>();

    k_lstm_main<<<dim3(GX, GY), 256, DYN_SMEM>>>(x, x_index, c0);

    k_fc1<<<dim3(Mm / 64, Bb / 64), 256>>>(fc1_w, fc1_b);
    k_fc2<<<Bb, 128>>>(fc2_w, fc2_b, out);
}

// round 12
// speedup vs baseline: 1.7508x; 1.0181x over previous
#include <cuda_runtime.h>
#include <cuda_bf16.h>
#include <stdint.h>

#define Bb 256
#define Tt 512
#define Ee 512
#define Hh 1024
#define G4 4096
#define Mm 1024
#define VOC 32001

#define GX 32              // n-tiles (32 h-cols -> N=128 with 4 gates)
#define GY 4               // batch groups (64 each -> M=64)
#define GRPBLK GX
#define NT 16              // K-tiles of 64 over K=1024 (h only)
#define NRES 7             // resident W_hh K-tiles; 7..15 streamed (4-stage)
#define BTILE 16384        // 128 rows x 128B
#define ATILE 8192         // 64 rows x 128B
#define BSTR_OFF (NRES * BTILE)          // 114688
#define A_OFF    (BSTR_OFF + 4 * BTILE)  // 180224
#define SG_OFF   (A_OFF + 4 * ATILE)     // 212992
#define DYN_SMEM (SG_OFF + 16384)        // 229376 (<= 232448 max)
#define GT_DYN   98304                   // k_gtab: 3 stages x (16K A + 16K B)

// ---------------- static device scratch ----------------
__device__ __align__(16) __nv_bfloat16 g_emb16[(size_t)VOC * Ee];      // 32.8 MB
__device__ __align__(16) __nv_bfloat16 g_Wi[(size_t)G4 * Ee];          // 4.2 MB
__device__ __align__(16) __nv_bfloat16 g_Wh[(size_t)G4 * Hh];          // 8.4 MB
__device__ __align__(16) __nv_bfloat16 g_gtab[(size_t)VOC * G4];       // 262 MB: Gtab[v] = W_ih @ emb[v]
__device__ float         g_bias[G4];
__device__ __align__(16) __nv_bfloat16 g_h[2][Bb * Hh];                // double buffered (full barrier/step)
__device__ float         g_hn[Bb * Hh];
__device__ float         g_z[Bb * Mm];
__device__ unsigned      g_bar4[4];                                    // per-gy step barrier

// ---------------- setup kernels ----------------
__global__ void k_setup_emb(const float* __restrict__ emb) {
    int i4 = blockIdx.x * blockDim.x + threadIdx.x;
    const int n4 = (VOC * Ee) / 4;
    if (i4 >= n4) return;
    float4 v = reinterpret_cast<const float4*>(emb)[i4];
    reinterpret_cast<__nv_bfloat162*>(g_emb16)[i4 * 2 + 0] = __floats2bfloat162_rn(v.x, v.y);
    reinterpret_cast<__nv_bfloat162*>(g_emb16)[i4 * 2 + 1] = __floats2bfloat162_rn(v.z, v.w);
}

__global__ void k_setup_w(const float* __restrict__ Wih, const float* __restrict__ Whh) {
    int i4 = blockIdx.x * blockDim.x + threadIdx.x;
    const int nW = (G4 * Hh) / 4;
    if (i4 < nW) {
        float4 v = *reinterpret_cast<const float4*>(&Whh[(size_t)i4 * 4]);
        reinterpret_cast<__nv_bfloat162*>(g_Wh)[i4 * 2 + 0] = __floats2bfloat162_rn(v.x, v.y);
        reinterpret_cast<__nv_bfloat162*>(g_Wh)[i4 * 2 + 1] = __floats2bfloat162_rn(v.z, v.w);
    }
    const int nI = (G4 * Ee) / 4;
    if (i4 < nI) {
        float4 v = *reinterpret_cast<const float4*>(&Wih[(size_t)i4 * 4]);
        reinterpret_cast<__nv_bfloat162*>(g_Wi)[i4 * 2 + 0] = __floats2bfloat162_rn(v.x, v.y);
        reinterpret_cast<__nv_bfloat162*>(g_Wi)[i4 * 2 + 1] = __floats2bfloat162_rn(v.z, v.w);
    }
}

__global__ void k_setup_state(const float* __restrict__ h0,
                              const float* __restrict__ b_ih, const float* __restrict__ b_hh) {
    int i = blockIdx.x * blockDim.x + threadIdx.x;
    if (i < Bb * Hh) g_h[0][i] = __float2bfloat16(h0[i]);
    if (i < G4)      g_bias[i] = b_ih[i] + b_hh[i];
    if (i < 4)       g_bar4[i] = 0u;
}

// ---------------- helpers ----------------
__device__ __forceinline__ void mma16816(float* d, const uint32_t* a, const uint32_t* b) {
    asm volatile(
        "mma.sync.aligned.m16n8k16.row.col.f32.bf16.bf16.f32 "
        "{%0,%1,%2,%3}, {%4,%5,%6,%7}, {%8,%9}, {%0,%1,%2,%3};\n"
        : "+f"(d[0]), "+f"(d[1]), "+f"(d[2]), "+f"(d[3])
        : "r"(a[0]), "r"(a[1]), "r"(a[2]), "r"(a[3]), "r"(b[0]), "r"(b[1]));
}

#define CP16(dst, src) \
    asm volatile("cp.async.cg.shared.global [%0], [%1], 16;\n" :: "r"(dst), "l"(src))
#define CP_COMMIT() asm volatile("cp.async.commit_group;\n")
#define LDM_X4(r0, r1, r2, r3, addr) \
    asm volatile("ldmatrix.sync.aligned.m8n8.x4.shared.b16 {%0,%1,%2,%3}, [%4];\n" \
                 : "=r"(r0), "=r"(r1), "=r"(r2), "=r"(r3) : "r"(addr))

__device__ __forceinline__ float sigf(float x) {
    return __fdividef(1.0f, 1.0f + __expf(-x));
}
__device__ __forceinline__ float tanhfast(float x) {
    return __fdividef(2.0f, 1.0f + __expf(-2.0f * x)) - 1.0f;
}

// ---------------- Gtab GEMM: Gtab[v][n] = sum_k emb16[v][k] * W_ih[n][k] ----------------
__global__ __launch_bounds__(256) void k_gtab() {
    extern __shared__ __align__(16) char gsm[];
    const uint32_t smb = (uint32_t)__cvta_generic_to_shared(gsm);
    const int tid = threadIdx.x;
    const int lane = tid & 31;
    const int wid = tid >> 5;
    const int n0 = blockIdx.x * 128;
    const int vb = blockIdx.y * 128;

    auto load = [&](int kt) {
#pragma unroll
        for (int i = 0; i < 4; ++i) {
            int id = tid + i * 256;
            int r = id >> 3, c = id & 7;
            int v = vb + r; if (v > VOC - 1) v = VOC - 1;
            uint32_t sw = (uint32_t)(r * 128 + ((c ^ (r & 7)) << 4));
            CP16(smb + (kt % 3) * 16384u + sw, g_emb16 + (size_t)v * Ee + kt * 64 + c * 8);
            CP16(smb + 49152u + (kt % 3) * 16384u + sw, g_Wi + (size_t)(n0 + r) * Ee + kt * 64 + c * 8);
        }
        CP_COMMIT();
    };

    const int mbase = (wid >> 2) * 64;
    const int nbase = (wid & 3) * 32;
    float acc[4][4][4];
#pragma unroll
    for (int mt = 0; mt < 4; ++mt)
#pragma unroll
        for (int nt = 0; nt < 4; ++nt)
#pragma unroll
            for (int e = 0; e < 4; ++e) acc[mt][nt][e] = 0.0f;

    load(0);
    load(1);
    for (int kt = 0; kt < 8; ++kt) {
        if (kt < 7) asm volatile("cp.async.wait_group 1;\n");
        else        asm volatile("cp.async.wait_group 0;\n");
        __syncthreads();
        if (kt + 2 < 8) load(kt + 2);
        const uint32_t ab = smb + (kt % 3) * 16384u;
        const uint32_t bbs = smb + 49152u + (kt % 3) * 16384u;
#pragma unroll
        for (int ks = 0; ks < 64; ks += 16) {
            uint32_t a[4][4];
#pragma unroll
            for (int mt = 0; mt < 4; ++mt) {
                int r = mbase + mt * 16 + (lane & 15);
                int ch = (ks >> 3) + (lane >> 4);
                LDM_X4(a[mt][0], a[mt][1], a[mt][2], a[mt][3],
                       ab + (uint32_t)(r * 128 + ((ch ^ (r & 7)) << 4)));
            }
            uint32_t b[2][4];
#pragma unroll
            for (int bt = 0; bt < 2; ++bt) {
                int gq = lane >> 3;
                int rn = nbase + bt * 16 + ((gq >> 1) << 3) + (lane & 7);
                int ch = (ks >> 3) + (gq & 1);
                LDM_X4(b[bt][0], b[bt][1], b[bt][2], b[bt][3],
                       bbs + (uint32_t)(rn * 128 + ((ch ^ (rn & 7)) << 4)));
            }
#pragma unroll
            for (int mt = 0; mt < 4; ++mt)
#pragma unroll
                for (int nt = 0; nt < 4; ++nt) {
                    uint32_t bf[2] = { b[nt >> 1][(nt & 1) * 2], b[nt >> 1][(nt & 1) * 2 + 1] };
                    mma16816(acc[mt][nt], a[mt], bf);
                }
        }
        __syncthreads();
    }

    const int fr = lane >> 2, fc = (lane & 3) * 2;
#pragma unroll
    for (int mt = 0; mt < 4; ++mt)
#pragma unroll
        for (int nt = 0; nt < 4; ++nt) {
            int c = n0 + nbase + nt * 8 + fc;
            int v0 = vb + mbase + mt * 16 + fr;
            int v1 = v0 + 8;
            if (v0 < VOC)
                *reinterpret_cast<__nv_bfloat162*>(g_gtab + (size_t)v0 * G4 + c) =
                    __floats2bfloat162_rn(acc[mt][nt][0], acc[mt][nt][1]);
            if (v1 < VOC)
                *reinterpret_cast<__nv_bfloat162*>(g_gtab + (size_t)v1 * G4 + c) =
                    __floats2bfloat162_rn(acc[mt][nt][2], acc[mt][nt][3]);
        }
}

// ---------------- persistent fused LSTM (K=1024, Gtab gather epilogue) ----------------
// grid (32, 4). Block tile: gates[64, 128] = h @ Wh_slice^T + Gtab + bias.
// Warps 0-3: mma, warp tile m32 x n64 (2x2). Warps 4-7: cp.async loaders.
// 4-stage pipeline, loads issued 3 tiles ahead. R8 barrier (red.release + spin).
__global__ void __launch_bounds__(256, 1)
k_lstm_main(const int* __restrict__ x, const int* __restrict__ x_index,
            const float* __restrict__ c0) {
    extern __shared__ __align__(16) char dynsm[];
    __shared__ float s_bias[128];

    const int tid = threadIdx.x;
    const int lane = tid & 31;
    const int wid = tid >> 5;
    const int gy = blockIdx.y;
    const int bx = blockIdx.x;
    const int b0 = gy * 64;
    const int hc0 = bx * 32;

    const uint32_t smb = (uint32_t)__cvta_generic_to_shared(dynsm);
    const uint32_t Bres = smb;
    const uint32_t Bstr = smb + BSTR_OFF;
    const uint32_t Ab   = smb + A_OFF;
    const uint32_t sGb  = smb + SG_OFF;
    float* sD = reinterpret_cast<float*>(dynsm + BSTR_OFF);   // overlays Bstr (33792B <= 65536B)
    const __nv_bfloat16* sG = reinterpret_cast<const __nv_bfloat16*>(dynsm + SG_OFF);

    if (tid < 128) s_bias[tid] = g_bias[(tid >> 5) * Hh + hc0 + (tid & 31)];

    // ---- resident Wh tiles 0..6 (rows n = gate*32+j over K cols) ----
    for (int i = tid; i < NRES * 1024; i += 256) {
        int kt = i >> 10, rem = i & 1023, n = rem >> 3, c = rem & 7;
        const __nv_bfloat16* src =
            g_Wh + (size_t)((n >> 5) * Hh + hc0 + (n & 31)) * Hh + kt * 64 + c * 8;
        CP16(Bres + (uint32_t)(kt * BTILE + n * 128 + ((c ^ (n & 7)) << 4)), src);
    }
    CP_COMMIT();
    asm volatile("cp.async.wait_group 0;\n");
    __syncthreads();

    // ---- loader assignments (warps 4-7) ----
    const bool loader = (wid >= 4);
    const int l7 = tid & 127;
    const int rb = l7 >> 3;   // 0..15
    const int cc = l7 & 7;
    uint32_t adst[4];
#pragma unroll
    for (int i = 0; i < 4; ++i) {
        int r = rb + 16 * i;
        adst[i] = (uint32_t)(r * 128 + ((cc ^ (r & 7)) << 4));
    }
    uint32_t bdst[8];
#pragma unroll
    for (int i = 0; i < 8; ++i) {
        int r = rb + 16 * i;
        bdst[i] = (uint32_t)(r * 128 + ((cc ^ (r & 7)) << 4));
    }
    const int sg_r = l7 >> 1;          // sG row 0..63
    const int sg_cb = (l7 & 1) * 8;    // chunk base

    // ---- mma warp config (warps 0-3): 2(m) x 2(n), warp tile m32 x n64 ----
    const int mbase = ((wid >> 1) & 1) * 32;
    const int nbase = (wid & 1) * 64;

    // ---- epilogue state: all threads own 8 (bb, jj) items, c in regs ----
    float creg[8];
    int xib[8];
    {
        const int jj = tid & 31;
#pragma unroll
        for (int w = 0; w < 8; ++w) {
            int bb = w * 8 + (tid >> 5);
            int b = b0 + bb;
            xib[w] = x_index[b];
            creg[w] = c0[(size_t)b * Hh + hc0 + jj];
        }
    }

    auto sG_load = [&](int t) {
        if (loader) {
            int tok = x[(size_t)(b0 + sg_r) * Tt + t];
            const __nv_bfloat16* gr = g_gtab + (size_t)tok * G4;
#pragma unroll
            for (int q = 0; q < 8; ++q) {
                int c = sg_cb + q;
                CP16(sGb + (uint32_t)(sg_r * 256 + c * 16), gr + (c >> 2) * Hh + hc0 + (c & 3) * 8);
            }
        }
        CP_COMMIT();
    };

    auto load_tile = [&](int kt, int t) {
        if (loader) {
            const uint32_t st = Ab + (uint32_t)(kt & 3) * ATILE;
            const __nv_bfloat16* hrd = g_h[t & 1];
#pragma unroll
            for (int i = 0; i < 4; ++i)
                CP16(st + adst[i], hrd + (size_t)(b0 + rb + 16 * i) * Hh + kt * 64 + cc * 8);
            if (kt >= NRES) {
                const uint32_t bs = Bstr + (uint32_t)(kt & 3) * BTILE;
#pragma unroll
                for (int i = 0; i < 8; ++i) {
                    int n = rb + 16 * i;
                    const __nv_bfloat16* src =
                        g_Wh + (size_t)((n >> 5) * Hh + hc0 + (n & 31)) * Hh + kt * 64 + cc * 8;
                    CP16(bs + bdst[i], src);
                }
            }
        }
        CP_COMMIT();
    };

    sG_load(0);
    load_tile(0, 0);
    load_tile(1, 0);
    load_tile(2, 0);

    for (int t = 0; t < Tt; ++t) {
        float acc[2][8][4];
#pragma unroll
        for (int mt = 0; mt < 2; ++mt)
#pragma unroll
            for (int nt = 0; nt < 8; ++nt)
#pragma unroll
                for (int e = 0; e < 4; ++e) acc[mt][nt][e] = 0.0f;

        for (int it = 0; it < NT; ++it) {
            if (it < NT - 2)      asm volatile("cp.async.wait_group 2;\n");
            else if (it < NT - 1) asm volatile("cp.async.wait_group 1;\n");
            else                  asm volatile("cp.async.wait_group 0;\n");
            __syncthreads();
            if (it + 3 < NT) load_tile(it + 3, t);

            if (wid < 4) {
                const uint32_t ab = Ab + (uint32_t)(it & 3) * ATILE;
                const uint32_t bb = (it < NRES) ? (Bres + (uint32_t)it * BTILE)
                                                : (Bstr + (uint32_t)(it & 3) * BTILE);
#pragma unroll
                for (int ks = 0; ks < 64; ks += 16) {
                    uint32_t a[2][4];
#pragma unroll
                    for (int mt = 0; mt < 2; ++mt) {
                        int r = mbase + mt * 16 + (lane & 15);
                        int ch = (ks >> 3) + (lane >> 4);
                        LDM_X4(a[mt][0], a[mt][1], a[mt][2], a[mt][3],
                               ab + (uint32_t)(r * 128 + ((ch ^ (r & 7)) << 4)));
                    }
                    uint32_t b[4][4];
#pragma unroll
                    for (int bt = 0; bt < 4; ++bt) {
                        int gq = lane >> 3;
                        int rn = nbase + bt * 16 + ((gq >> 1) << 3) + (lane & 7);
                        int ch = (ks >> 3) + (gq & 1);
                        LDM_X4(b[bt][0], b[bt][1], b[bt][2], b[bt][3],
                               bb + (uint32_t)(rn * 128 + ((ch ^ (rn & 7)) << 4)));
                    }
#pragma unroll
                    for (int mt = 0; mt < 2; ++mt)
#pragma unroll
                        for (int nt = 0; nt < 8; ++nt) {
                            uint32_t bf[2] = { b[nt >> 1][(nt & 1) * 2], b[nt >> 1][(nt & 1) * 2 + 1] };
                            mma16816(acc[mt][nt], a[mt], bf);
                        }
                }
            }
        }
        __syncthreads();   // mma done; Bstr stages reusable as sD

        // ---- stage D: sD[m][n], rows padded to 132 floats (overlays Bstr) ----
        if (wid < 4) {
            const int fr = lane >> 2, fc = (lane & 3) * 2;
#pragma unroll
            for (int mt = 0; mt < 2; ++mt)
#pragma unroll
                for (int nt = 0; nt < 8; ++nt) {
                    int m = mbase + mt * 16 + fr;
                    int n = nbase + nt * 8 + fc;
                    sD[m * 132 + n]           = acc[mt][nt][0];
                    sD[m * 132 + n + 1]       = acc[mt][nt][1];
                    sD[(m + 8) * 132 + n]     = acc[mt][nt][2];
                    sD[(m + 8) * 132 + n + 1] = acc[mt][nt][3];
                }
        }
        __syncthreads();

        // ---- pointwise LSTM update: all 8 warps, 2048 items ----
        {
            const int jj = tid & 31;
            __nv_bfloat16* hwr = g_h[(t + 1) & 1];
#pragma unroll
            for (int w = 0; w < 8; ++w) {
                int bb = w * 8 + (tid >> 5);
                int b = b0 + bb;
                const float* row = sD + bb * 132;
                const __nv_bfloat16* grow = sG + bb * 128;
                float ig = row[jj]      + __bfloat162float(grow[jj])      + s_bias[jj];
                float fg = row[32 + jj] + __bfloat162float(grow[32 + jj]) + s_bias[32 + jj];
                float gg = row[64 + jj] + __bfloat162float(grow[64 + jj]) + s_bias[64 + jj];
                float og = row[96 + jj] + __bfloat162float(grow[96 + jj]) + s_bias[96 + jj];
                float cv = sigf(fg) * creg[w] + sigf(ig) * tanhfast(gg);
                creg[w] = cv;
                float hv = sigf(og) * tanhfast(cv);
                hwr[(size_t)b * Hh + hc0 + jj] = __float2bfloat16(hv);
                if (xib[w] == t) g_hn[(size_t)b * Hh + hc0 + jj] = hv;
            }
        }
        __syncthreads();   // h(t+1) slice written; sG buffer free

        if (t + 1 < Tt) {
            sG_load(t + 1);   // token-only dependence; overlaps barrier
            if (tid == 0) {
                unsigned* bar = &g_bar4[gy];
                asm volatile("red.release.gpu.global.add.u32 [%0], %1;" :: "l"(bar), "r"(1u) : "memory");
                unsigned target = (unsigned)(t + 1) * GRPBLK;
                unsigned v;
                do {
                    asm volatile("ld.acquire.gpu.global.u32 %0, [%1];" : "=r"(v) : "l"(bar) : "memory");
                } while (v < target);
            }
            __syncthreads();
            load_tile(0, t + 1);
            load_tile(1, t + 1);
            load_tile(2, t + 1);
        }
    }
}

// ---------------- fc1: z = tanh(hn @ fc1_w^T + fc1_b), fp32 ----------------
__global__ __launch_bounds__(256) void k_fc1(const float* __restrict__ fc1_w,
                                             const float* __restrict__ fc1_b) {
    __shared__ float sA[16][68];
    __shared__ float sB[16][68];
    const int tid = threadIdx.x;
    const int b0 = blockIdx.y * 64;
    const int n0 = blockIdx.x * 64;
    const int tx = tid & 15, ty = tid >> 4;
    const int lr = tid & 63;
    const int lc4 = (tid >> 6) * 4;

    float acc[4][4];
#pragma unroll
    for (int i = 0; i < 4; ++i)
#pragma unroll
        for (int jn = 0; jn < 4; ++jn) acc[i][jn] = 0.0f;

    for (int k0 = 0; k0 < Hh; k0 += 16) {
        float4 va = *reinterpret_cast<const float4*>(&g_hn[(size_t)(b0 + lr) * Hh + k0 + lc4]);
        float4 vb = *reinterpret_cast<const float4*>(&fc1_w[(size_t)(n0 + lr) * Hh + k0 + lc4]);
        __syncthreads();
        sA[lc4 + 0][lr] = va.x; sA[lc4 + 1][lr] = va.y; sA[lc4 + 2][lr] = va.z; sA[lc4 + 3][lr] = va.w;
        sB[lc4 + 0][lr] = vb.x; sB[lc4 + 1][lr] = vb.y; sB[lc4 + 2][lr] = vb.z; sB[lc4 + 3][lr] = vb.w;
        __syncthreads();
#pragma unroll
        for (int k = 0; k < 16; ++k) {
            float4 ra4 = *reinterpret_cast<const float4*>(&sA[k][ty * 4]);
            float4 rb4 = *reinterpret_cast<const float4*>(&sB[k][tx * 4]);
            float ra[4] = {ra4.x, ra4.y, ra4.z, ra4.w};
            float rb[4] = {rb4.x, rb4.y, rb4.z, rb4.w};
#pragma unroll
            for (int i = 0; i < 4; ++i)
#pragma unroll
                for (int jn = 0; jn < 4; ++jn) acc[i][jn] += ra[i] * rb[jn];
        }
    }
#pragma unroll
    for (int i = 0; i < 4; ++i)
#pragma unroll
        for (int jn = 0; jn < 4; ++jn) {
            int bb = b0 + ty * 4 + i;
            int nn = n0 + tx * 4 + jn;
            g_z[(size_t)bb * Mm + nn] = tanhf(acc[i][jn] + fc1_b[nn]);
        }
}

// ---------------- fc2 + log_softmax (O=2) ----------------
__global__ __launch_bounds__(128) void k_fc2(const float* __restrict__ fc2_w,
                                             const float* __restrict__ fc2_b,
                                             float* __restrict__ out) {
    const int b = blockIdx.x;
    const int tid = threadIdx.x;
    float p0 = 0.f, p1 = 0.f;
    for (int k = tid; k < Mm; k += 128) {
        float zv = g_z[(size_t)b * Mm + k];
        p0 += zv * fc2_w[k];
        p1 += zv * fc2_w[Mm + k];
    }
#pragma unroll
    for (int off = 16; off; off >>= 1) {
        p0 += __shfl_down_sync(0xffffffffu, p0, off);
        p1 += __shfl_down_sync(0xffffffffu, p1, off);
    }
    __shared__ float s0[4], s1[4];
    if ((tid & 31) == 0) { s0[tid >> 5] = p0; s1[tid >> 5] = p1; }
    __syncthreads();
    if (tid == 0) {
        float l0 = s0[0] + s0[1] + s0[2] + s0[3] + fc2_b[0];
        float l1 = s1[0] + s1[1] + s1[2] + s1[3] + fc2_b[1];
        float mx = fmaxf(l0, l1);
        float lse = mx + logf(expf(l0 - mx) + expf(l1 - mx));
        out[b * 2 + 0] = l0 - lse;
        out[b * 2 + 1] = l1 - lse;
    }
}

// ---------------- launch ----------------
extern "C" void kernel_launch(void* const* d_in, const int* in_sizes, int n_in,
                              void* d_out, int out_size) {
    const int*   x       = (const int*)d_in[0];
    const int*   x_index = (const int*)d_in[1];
    const float* emb     = (const float*)d_in[2];
    const float* W_ih    = (const float*)d_in[3];
    const float* W_hh    = (const float*)d_in[4];
    const float* b_ih    = (const float*)d_in[5];
    const float* b_hh    = (const float*)d_in[6];
    const float* fc1_w   = (const float*)d_in[7];
    const float* fc1_b   = (const float*)d_in[8];
    const float* fc2_w   = (const float*)d_in[9];
    const float* fc2_b   = (const float*)d_in[10];
    const float* h0      = (const float*)d_in[11];
    const float* c0      = (const float*)d_in[12];
    float* out = (float*)d_out;

    (void)in_sizes; (void)n_in; (void)out_size;

    cudaFuncSetAttribute(k_lstm_main, cudaFuncAttributeMaxDynamicSharedMemorySize, DYN_SMEM);
    cudaFuncSetAttribute(k_gtab, cudaFuncAttributeMaxDynamicSharedMemorySize, GT_DYN);

    k_setup_emb<<<(VOC * Ee / 4 + 255) / 256, 256>>>(emb);
    k_setup_w<<<(G4 * Hh / 4 + 255) / 256, 256>>>(W_ih, W_hh);
    k_setup_state<<<(Bb * Hh + 255) / 256, 256>>>(h0, b_ih, b_hh);

    k_gtab<<<dim3(G4 / 128, (VOC + 127) / 128), 256, GT_DYN>>>();

    k_lstm_main<<<dim3(GX, GY), 256, DYN_SMEM>>>(x, x_index, c0);

    k_fc1<<<dim3(Mm / 64, Bb / 64), 256>>>(fc1_w, fc1_b);
    k_fc2<<<Bb, 128>>>(fc2_w, fc2_b, out);
}